// round 15
// baseline (speedup 1.0000x reference)
#include <cuda_runtime.h>

#define BB 32
#define NFULL 8192
#define STRIDE_R (NFULL-1)          /* 8191 rows per batch */
#define CC 16
#define CKD 64
#define NLEV 13
#define SPEC (BB*64*CKD*2)          /* 524288 floats per level */
#define TWTOT (64*(NFULL-1))        /* 524224 */

typedef unsigned long long ull;

// ---------------- static device scratch ----------------
__device__ float g_sbuf[BB*STRIDE_R*CKD];
__device__ float g_dbuf[BB*STRIDE_R*CKD];   // used for deep levels (6..12) only
__device__ float g_Ud[BB*STRIDE_R*CKD];
__device__ float g_Us[BB*STRIDE_R*CKD];
__device__ float g_DhatL[NLEV*SPEC];
__device__ float g_ShatL[NLEV*SPEC];
__device__ float g_UdhatL[NLEV*SPEC];
__device__ float g_UshatL[NLEV*SPEC];
__device__ float g_partD[14*SPEC];
__device__ float g_partS[14*SPEC];
__device__ float g_twc[TWTOT];
__device__ float g_tws[TWTOT];
__device__ float g_wT[6][CKD*CKD*64];   // [which][f][i][o]
__device__ float g_ecs[8][4];
__device__ float g_ecd[8][4];
__device__ float g_rce[8][4];
__device__ float g_rco[8][4];

// ---------------- f32x2 helpers ----------------
__device__ __forceinline__ void ffma2(ull& d, ull a, ull b) {
    asm("fma.rn.f32x2 %0, %1, %2, %0;" : "+l"(d) : "l"(a), "l"(b));
}
__device__ __forceinline__ ull pack2(float lo, float hi) {
    ull r;
    asm("mov.b64 %0, {%1, %2};" : "=l"(r) : "f"(lo), "f"(hi));
    return r;
}
__device__ __forceinline__ void unpack2(ull v, float& lo, float& hi) {
    asm("mov.b64 {%0, %1}, %2;" : "=f"(lo), "=f"(hi) : "l"(v));
}

// ---------------- Alpert multiwavelet filter construction (k=4, legendre) ------
__device__ double dproj(const double* a, int la, const double* b, int lb, bool upper) {
    double prod[16];
    int n = la + lb - 1;
    for (int t = 0; t < n; ++t) prod[t] = 0.0;
    for (int i = 0; i < la; ++i)
        for (int j = 0; j < lb; ++j)
            prod[i + j] += a[i] * b[j];
    double s = 0.0;
    double ph = 1.0;
    for (int t = 0; t < n; ++t) {
        ph *= 0.5;                       // ph = 0.5^(t+1), exact
        double p = prod[t];
        if (fabs(p) < 1e-8) p = 0.0;
        double w = (upper ? (1.0 - ph) : ph) / (double)(t + 1);
        s += p * w;
    }
    return s;
}

__device__ __forceinline__ double dpv(const double* c, double x) {
    return c[0] + x * (c[1] + x * (c[2] + x * c[3]));
}

__global__ void init_filters() {
    if (blockIdx.x != 0 || threadIdx.x != 0) return;
    const double legp[4][4] = {
        { 1.0,  0.0, 0.0, 0.0},
        { 0.0,  1.0, 0.0, 0.0},
        {-0.5,  0.0, 1.5, 0.0},
        { 0.0, -1.5, 0.0, 2.5}
    };
    double phi[4][4], phi2[4][4];
    for (int ki = 0; ki < 4; ++ki) {
        for (int pass = 0; pass < 2; ++pass) {
            double a0 = -1.0, a1 = (pass == 0) ? 2.0 : 4.0;
            double r[8]; for (int j = 0; j < 8; ++j) r[j] = 0.0;
            r[0] = legp[ki][ki];
            int rd = 0;
            for (int i = ki - 1; i >= 0; --i) {
                double nr[8]; for (int j = 0; j < 8; ++j) nr[j] = 0.0;
                for (int j = 0; j <= rd; ++j) { nr[j] += r[j] * a0; nr[j + 1] += r[j] * a1; }
                nr[0] += legp[ki][i];
                ++rd;
                for (int j = 0; j < 8; ++j) r[j] = nr[j];
            }
            double sc = (pass == 0) ? sqrt(2.0 * ki + 1.0) : sqrt(2.0) * sqrt(2.0 * ki + 1.0);
            for (int j = 0; j < 4; ++j) {
                double v = (j <= ki) ? r[j] * sc : 0.0;
                if (pass == 0) phi[ki][j] = v; else phi2[ki][j] = v;
            }
        }
    }
    double psi1[4][4], psi2[4][4];
    for (int i = 0; i < 4; ++i) for (int j = 0; j < 4; ++j) { psi1[i][j] = 0.0; psi2[i][j] = 0.0; }
    for (int ki = 0; ki < 4; ++ki) {
        for (int t = 0; t < 4; ++t) psi1[ki][t] = phi2[ki][t];
        for (int i = 0; i < 4; ++i) {
            double p = dproj(phi2[ki], ki + 1, phi[i], i + 1, false);
            for (int t = 0; t < 4; ++t) { psi1[ki][t] -= p * phi[i][t]; psi2[ki][t] -= p * phi[i][t]; }
        }
        for (int j = 0; j < ki; ++j) {
            double p = dproj(phi2[ki], ki + 1, psi1[j], 4, false);
            for (int t = 0; t < 4; ++t) { psi1[ki][t] -= p * psi1[j][t]; psi2[ki][t] -= p * psi2[j][t]; }
        }
        double n1 = dproj(psi1[ki], 4, psi1[ki], 4, false);
        double n2 = dproj(psi2[ki], 4, psi2[ki], 4, true);
        double nrm = sqrt(n1 + n2);
        for (int t = 0; t < 4; ++t) { psi1[ki][t] /= nrm; psi2[ki][t] /= nrm; }
        for (int t = 0; t < 4; ++t) {
            if (fabs(psi1[ki][t]) < 1e-8) psi1[ki][t] = 0.0;
            if (fabs(psi2[ki][t]) < 1e-8) psi2[ki][t] = 0.0;
        }
    }
    const double xm[4] = {0.06943184420297371, 0.33000947820757187,
                          0.66999052179242813, 0.93056815579702623};
    const double wm[4] = {0.17392742256872692, 0.32607257743127305,
                          0.32607257743127305, 0.17392742256872692};
    double H0[4][4], H1[4][4], G0[4][4], G1[4][4];
    double s2 = sqrt(2.0);
    for (int ki = 0; ki < 4; ++ki) {
        for (int kp = 0; kp < 4; ++kp) {
            double h0 = 0, h1 = 0, g0 = 0, g1 = 0;
            for (int m = 0; m < 4; ++m) {
                double pb = dpv(phi[kp], xm[m]);
                h0 += wm[m] * dpv(phi[ki],  xm[m] * 0.5) * pb;
                g0 += wm[m] * dpv(psi1[ki], xm[m] * 0.5) * pb;
                h1 += wm[m] * dpv(phi[ki],  (xm[m] + 1.0) * 0.5) * pb;
                g1 += wm[m] * dpv(psi2[ki], (xm[m] + 1.0) * 0.5) * pb;
            }
            H0[ki][kp] = h0 / s2; H1[ki][kp] = h1 / s2;
            G0[ki][kp] = g0 / s2; G1[ki][kp] = g1 / s2;
        }
    }
    for (int i = 0; i < 4; ++i) for (int j = 0; j < 4; ++j) {
        if (fabs(H0[i][j]) < 1e-8) H0[i][j] = 0.0;
        if (fabs(H1[i][j]) < 1e-8) H1[i][j] = 0.0;
        if (fabs(G0[i][j]) < 1e-8) G0[i][j] = 0.0;
        if (fabs(G1[i][j]) < 1e-8) G1[i][j] = 0.0;
    }
    for (int r = 0; r < 4; ++r) for (int c = 0; c < 4; ++c) {
        g_ecs[r][c]     = (float)H0[c][r];
        g_ecs[r + 4][c] = (float)H1[c][r];
        g_ecd[r][c]     = (float)G0[c][r];
        g_ecd[r + 4][c] = (float)G1[c][r];
        g_rce[r][c]     = (float)H0[r][c];
        g_rce[r + 4][c] = (float)G0[r][c];
        g_rco[r][c]     = (float)H1[r][c];
        g_rco[r + 4][c] = (float)G1[r][c];
    }
}

// ---------------- twiddles: per level sections, cos/sin(2*pi*f*n/M) ------------
__global__ void fill_tw() {
    int idx = blockIdx.x * blockDim.x + threadIdx.x;
    if (idx >= TWTOT) return;
    int off = 0, M = 0;
    for (int lev = 0; lev < NLEV; ++lev) {
        M = NFULL >> (lev + 1);
        int sz = 64 * M;
        if (idx < off + sz) break;
        off += sz;
    }
    int loc = idx - off;
    int f = loc / M;
    int n = loc % M;
    int r = (int)(((long long)f * n) % M);
    float ang = 2.0f * (float)r / (float)M;
    float s, c;
    sincospif(ang, &s, &c);
    g_twc[idx] = c;
    g_tws[idx] = s;
}

// ---------------- weight transpose via smem tiles (coalesced both sides) -------
__global__ void k_transpose_w(const float* __restrict__ a0, const float* __restrict__ a1,
                              const float* __restrict__ a2, const float* __restrict__ a3,
                              const float* __restrict__ a4, const float* __restrict__ a5) {
    __shared__ float tile[64][65];
    int i = blockIdx.x;      // 0..63
    int w = blockIdx.y;      // 0..5
    const float* src = (w == 0) ? a0 : (w == 1) ? a1 : (w == 2) ? a2
                     : (w == 3) ? a3 : (w == 4) ? a4 : a5;
    int t = threadIdx.x;
    for (int q = t; q < 4096; q += 256) {
        int o = q >> 6, f = q & 63;
        tile[o][f] = src[(i * 64 + o) * 64 + f];
    }
    __syncthreads();
    for (int q = t; q < 4096; q += 256) {
        int f = q >> 6, o = q & 63;
        g_wT[w][f * 4096 + i * 64 + o] = tile[o][f];
    }
}

// ---------------- wavelet decomposition (levels 0..5): s-only output -----------
__global__ void k_decompose(const float* __restrict__ xin, int xoff, int xstride,
                            int off, int M) {
    int idx = blockIdx.x * blockDim.x + threadIdx.x;
    int tot = BB * M * CC;
    if (idx >= tot) return;
    int c = idx & 15;
    int m = (idx >> 4) % M;
    int b = idx / (CC * M);
    const float4* xi = (const float4*)xin;
    size_t r0 = ((size_t)b * xstride + xoff + 2 * m) * CC + c;
    float4 e = xi[r0];
    float4 o = xi[r0 + CC];
    float a[8] = {e.x, e.y, e.z, e.w, o.x, o.y, o.z, o.w};
    float sv[4] = {0, 0, 0, 0};
#pragma unroll
    for (int r = 0; r < 8; ++r) {
#pragma unroll
        for (int kk = 0; kk < 4; ++kk)
            sv[kk] += a[r] * g_ecs[r][kk];
    }
    size_t wrow = ((size_t)b * STRIDE_R + off + m) * CC + c;
    ((float4*)g_sbuf)[wrow] = make_float4(sv[0], sv[1], sv[2], sv[3]);
}

// ---------------- fused decomposition for levels 6..12 (smem chain) ------------
__global__ void k_deepdec() {
    int b = blockIdx.x;
    int t = threadIdx.x;
    __shared__ float cur[128 * 64];
    const float* src = g_sbuf + ((size_t)b * STRIDE_R + (NFULL - 256)) * 64;
    for (int q = t; q < 128 * 16; q += 256) {
        int r = q >> 4, c4 = (q & 15) << 2;
        *(float4*)&cur[r * 64 + c4] = *(const float4*)&src[r * 64 + c4];
    }
    __syncthreads();
    for (int lev = 6; lev < 13; ++lev) {
        int M = 4096 >> lev;
        int off = NFULL - (NFULL >> lev);
        int nu = M * 16;
        float4 sv[4]; int has[4] = {0, 0, 0, 0};
#pragma unroll
        for (int qi = 0; qi < 4; ++qi) {
            int q = t + qi * 256;
            if (q < nu) {
                int c = q & 15, m = q >> 4;
                const float* r0 = &cur[(2 * m) * 64 + c * 4];
                const float* r1 = &cur[(2 * m + 1) * 64 + c * 4];
                float a[8] = {r0[0], r0[1], r0[2], r0[3], r1[0], r1[1], r1[2], r1[3]};
                float s4[4] = {0, 0, 0, 0}, d4[4] = {0, 0, 0, 0};
#pragma unroll
                for (int r = 0; r < 8; ++r)
#pragma unroll
                    for (int kk = 0; kk < 4; ++kk) {
                        s4[kk] += a[r] * g_ecs[r][kk];
                        d4[kk] += a[r] * g_ecd[r][kk];
                    }
                size_t wrow = ((size_t)b * STRIDE_R + off + m) * 64 + c * 4;
                *(float4*)&g_sbuf[wrow] = make_float4(s4[0], s4[1], s4[2], s4[3]);
                *(float4*)&g_dbuf[wrow] = make_float4(d4[0], d4[1], d4[2], d4[3]);
                sv[qi] = make_float4(s4[0], s4[1], s4[2], s4[3]);
                has[qi] = 1;
            }
        }
        __syncthreads();
#pragma unroll
        for (int qi = 0; qi < 4; ++qi) {
            int q = t + qi * 256;
            if (has[qi]) {
                int c = q & 15, m = q >> 4;
                *(float4*)&cur[m * 64 + c * 4] = sv[qi];
            }
        }
        __syncthreads();
    }
}

// ---------------- forward truncated DFT, all levels in one launch --------------
// D-branch (which==0) for levels 0..5 recomputes d in the staging loop from the
// parent signal (bit-identical to the old decompose d), so d never hits DRAM.
__global__ void k_fwd_all(const float* __restrict__ xin) {
    int cu = blockIdx.x;
    int b = blockIdx.y;
    int which = blockIdx.z;
    int lev, ch;
    if (cu < 8)       { lev = 0; ch = cu; }
    else if (cu < 12) { lev = 1; ch = cu - 8; }
    else if (cu < 14) { lev = 2; ch = cu - 12; }
    else              { lev = cu - 11; ch = 0; }
    int M = 4096 >> lev;
    int off = NFULL - (NFULL >> lev);
    int l = M / 2 + 1; if (l > 64) l = 64;
    int nch = (lev == 0) ? 8 : (lev == 1) ? 4 : (lev == 2) ? 2 : 1;
    int chunk = M / nch;
    const float* src = (which ? g_sbuf : g_dbuf) + ((size_t)b * STRIDE_R + off) * 64;
    // parent signal for fused d computation (levels 0..5)
    const float* par; size_t pstride; int poff;
    if (lev == 0) { par = xin; pstride = NFULL; poff = 0; }
    else { par = g_sbuf; pstride = STRIDE_R; poff = NFULL - (NFULL >> (lev - 1)); }
    int fuse_d = (which == 0 && lev <= 5);
    float* dst;
    if (nch == 1) {
        dst = (which ? g_ShatL : g_DhatL) + (size_t)lev * SPEC;
    } else {
        int ub = (lev == 0) ? 0 : (lev == 1) ? 8 : 12;
        dst = (which ? g_partS : g_partD) + (size_t)(ub + ch) * SPEC;
    }
    const float* twc = g_twc + (size_t)off * 64;
    const float* tws = g_tws + (size_t)off * 64;
    int n0 = ch * chunk;
    int n1 = n0 + chunk;
    int t = threadIdx.x;
    int fr = t >> 4;
    int jc = t & 15;

    __shared__ float xs[32][64];
    __shared__ ull tw[64][32];   // (c, -s)

    ull acc[4][4];
#pragma unroll
    for (int u = 0; u < 4; ++u)
#pragma unroll
        for (int v = 0; v < 4; ++v) acc[u][v] = 0ULL;

    for (int nb = n0; nb < n1; nb += 32) {
        int cnt = n1 - nb; if (cnt > 32) cnt = 32;
        if (fuse_d) {
            // stage d computed from parent rows 2m, 2m+1 (levels 0..5: cnt==32)
            for (int q = t; q < 512; q += 256) {
                int ml = q >> 4, c4 = (q & 15) << 2;
                int m = nb + ml;
                size_t xr = ((size_t)b * pstride + poff + 2 * m) * 64 + c4;
                float4 e = *(const float4*)&par[xr];
                float4 o = *(const float4*)&par[xr + 64];
                float a[8] = {e.x, e.y, e.z, e.w, o.x, o.y, o.z, o.w};
                float d4[4] = {0, 0, 0, 0};
#pragma unroll
                for (int r = 0; r < 8; ++r)
#pragma unroll
                    for (int kk = 0; kk < 4; ++kk)
                        d4[kk] += a[r] * g_ecd[r][kk];
                *(float4*)&xs[ml][c4] = make_float4(d4[0], d4[1], d4[2], d4[3]);
            }
        } else {
            for (int q = t; q < cnt * 16; q += 256) {
                int nn = q >> 4, jj = (q & 15) << 2;
                *(float4*)&xs[nn][jj] = *(const float4*)&src[(size_t)(nb + nn) * 64 + jj];
            }
        }
        for (int q = t; q < 2048; q += 256) {
            int f = q >> 5, nn = q & 31;
            float c = 0.0f, s = 0.0f;
            if (nn < cnt) { c = twc[f * M + nb + nn]; s = tws[f * M + nb + nn]; }
            tw[f][nn] = pack2(c, -s);
        }
        __syncthreads();
        if (cnt == 32) {
#pragma unroll 2
            for (int nn = 0; nn < 32; ++nn) {
                float4 xv = *(const float4*)&xs[nn][jc << 2];
                ull xx0 = pack2(xv.x, xv.x);
                ull xx1 = pack2(xv.y, xv.y);
                ull xx2 = pack2(xv.z, xv.z);
                ull xx3 = pack2(xv.w, xv.w);
#pragma unroll
                for (int u = 0; u < 4; ++u) {
                    ull csp = tw[fr + 16 * u][nn];
                    ffma2(acc[u][0], csp, xx0);
                    ffma2(acc[u][1], csp, xx1);
                    ffma2(acc[u][2], csp, xx2);
                    ffma2(acc[u][3], csp, xx3);
                }
            }
        } else {
            for (int nn = 0; nn < cnt; ++nn) {
                float4 xv = *(const float4*)&xs[nn][jc << 2];
                ull xx0 = pack2(xv.x, xv.x);
                ull xx1 = pack2(xv.y, xv.y);
                ull xx2 = pack2(xv.z, xv.z);
                ull xx3 = pack2(xv.w, xv.w);
#pragma unroll
                for (int u = 0; u < 4; ++u) {
                    ull csp = tw[fr + 16 * u][nn];
                    ffma2(acc[u][0], csp, xx0);
                    ffma2(acc[u][1], csp, xx1);
                    ffma2(acc[u][2], csp, xx2);
                    ffma2(acc[u][3], csp, xx3);
                }
            }
        }
        __syncthreads();
    }
#pragma unroll
    for (int u = 0; u < 4; ++u) {
        int f = fr + 16 * u;
        if (f < l) {
            size_t base = ((((size_t)b * 64 + f) * 64) + (jc << 2)) * 2;
            ulonglong2 s0; s0.x = acc[u][0]; s0.y = acc[u][1];
            ulonglong2 s1; s1.x = acc[u][2]; s1.y = acc[u][3];
            *(ulonglong2*)&dst[base]     = s0;
            *(ulonglong2*)&dst[base + 4] = s1;
        }
    }
}

// ---------------- per-mode complex mixing, all levels ----------------
__global__ void k_mix_all() {
    int lev = blockIdx.x >> 6;
    int f = blockIdx.x & 63;
    int M = 4096 >> lev;
    int l = M / 2 + 1; if (l > 64) l = 64;
    if (f >= l) return;
    int b0 = blockIdx.y * 8;
    int t = threadIdx.x;
    const float2* D2 = (const float2*)(g_DhatL + (size_t)lev * SPEC);
    const float2* S2 = (const float2*)(g_ShatL + (size_t)lev * SPEC);
    __shared__ ull Dp[8][64], Dn[8][64], Sp[8][64], Sn[8][64];
    __shared__ float wsm[6][16][64];
    for (int q = t; q < 8 * 64; q += 256) {
        int bb = q >> 6, i = q & 63;
        size_t base = ((size_t)(b0 + bb) * 64 + f) * 64 + i;
        float2 dv, sv;
        if (lev < 3) {
            int nch = (lev == 0) ? 8 : (lev == 1) ? 4 : 2;
            int ub  = (lev == 0) ? 0 : (lev == 1) ? 8 : 12;
            float dr = 0.0f, di = 0.0f, sr = 0.0f, si = 0.0f;
            for (int c = 0; c < nch; ++c) {
                const float2* Pd = (const float2*)(g_partD + (size_t)(ub + c) * SPEC);
                const float2* Ps = (const float2*)(g_partS + (size_t)(ub + c) * SPEC);
                float2 a = Pd[base];
                float2 e = Ps[base];
                dr += a.x; di += a.y;
                sr += e.x; si += e.y;
            }
            dv = make_float2(dr, di);
            sv = make_float2(sr, si);
        } else {
            dv = D2[base];
            sv = S2[base];
        }
        Dp[bb][i] = pack2(dv.x, dv.y);
        Dn[bb][i] = pack2(-dv.y, dv.x);
        Sp[bb][i] = pack2(sv.x, sv.y);
        Sn[bb][i] = pack2(-sv.y, sv.x);
    }
    int o = t & 63;
    int bs = t >> 6;
    ull ud[2] = {0ULL, 0ULL}, us[2] = {0ULL, 0ULL};
    for (int ib = 0; ib < 64; ib += 16) {
        __syncthreads();
        for (int q = t; q < 16 * 64; q += 256) {
            int ii = q >> 6, oo = q & 63;
            int gi = f * 4096 + (ib + ii) * 64 + oo;
#pragma unroll
            for (int w = 0; w < 6; ++w) wsm[w][ii][oo] = g_wT[w][gi];
        }
        __syncthreads();
#pragma unroll 4
        for (int ii = 0; ii < 16; ++ii) {
            int i = ib + ii;
            float war = wsm[0][ii][o], wai = wsm[1][ii][o];
            float wbr = wsm[2][ii][o], wbi = wsm[3][ii][o];
            float wcr = wsm[4][ii][o], wci = wsm[5][ii][o];
            ull arr = pack2(war, war), aii = pack2(wai, wai);
            ull brr = pack2(wbr, wbr), bii = pack2(wbi, wbi);
            ull crr = pack2(wcr, wcr), cii = pack2(wci, wci);
#pragma unroll
            for (int q = 0; q < 2; ++q) {
                int bb = bs + 4 * q;
                ull dp = Dp[bb][i], dn = Dn[bb][i];
                ull sp = Sp[bb][i], sn = Sn[bb][i];
                ffma2(ud[q], arr, dp);
                ffma2(ud[q], aii, dn);
                ffma2(ud[q], brr, sp);
                ffma2(ud[q], bii, sn);
                ffma2(us[q], crr, dp);
                ffma2(us[q], cii, dn);
            }
        }
    }
    float alpha = (f == 0 || 2 * f == M) ? 1.0f : 2.0f;
    float sc = alpha / (float)M;
    float2* U2 = (float2*)(g_UdhatL + (size_t)lev * SPEC);
    float2* V2 = (float2*)(g_UshatL + (size_t)lev * SPEC);
#pragma unroll
    for (int q = 0; q < 2; ++q) {
        int b = b0 + bs + 4 * q;
        size_t base = ((size_t)b * 64 + f) * 64 + o;
        float ur, uv, vr, vv;
        unpack2(ud[q], ur, uv);
        unpack2(us[q], vr, vv);
        U2[base] = make_float2(ur * sc, uv * sc);
        V2[base] = make_float2(vr * sc, vv * sc);
    }
}

// ---------------- inverse DFT for deep levels 6..12 only -----------------------
__global__ void k_inv_deep() {
    int lev = 6 + blockIdx.x;
    int b = blockIdx.y;
    int which = blockIdx.z;
    int M = 4096 >> lev;
    int off = NFULL - (NFULL >> lev);
    int l = M / 2 + 1; if (l > 64) l = 64;
    const float4* spec4 = (const float4*)((which ? g_UshatL : g_UdhatL) + (size_t)lev * SPEC);
    float* out = (which ? g_Us : g_Ud) + ((size_t)b * STRIDE_R + off) * 64;
    const float* twc = g_twc + (size_t)off * 64;
    const float* tws = g_tws + (size_t)off * 64;
    int t = threadIdx.x;
    int nr = t >> 4;
    int jc = t & 15;

    __shared__ float Sr[32][64], Si[32][64];
    __shared__ float2 tw[64][32];

    ull acc[4][2];
#pragma unroll
    for (int u = 0; u < 4; ++u) { acc[u][0] = 0ULL; acc[u][1] = 0ULL; }

    for (int fb = 0; fb < l; fb += 32) {
        int cnt = l - fb; if (cnt > 32) cnt = 32;
        for (int q = t; q < cnt * 32; q += 256) {
            int ff = q >> 5, jp = (q & 31) << 1;
            float4 sv = spec4[((size_t)b * 64 + fb + ff) * 32 + (q & 31)];
            Sr[ff][jp] = sv.x; Si[ff][jp] = sv.y;
            Sr[ff][jp + 1] = sv.z; Si[ff][jp + 1] = sv.w;
        }
        for (int q = t; q < 2048; q += 256) {
            int nn = q & 63, ff = q >> 6;
            float c = 0.0f, s = 0.0f;
            if (ff < cnt && nn < M) { c = twc[(fb + ff) * M + nn]; s = tws[(fb + ff) * M + nn]; }
            tw[nn][ff] = make_float2(c, -s);
        }
        __syncthreads();
        for (int ff = 0; ff < cnt; ++ff) {
            ulonglong2 srp = *(const ulonglong2*)&Sr[ff][jc << 2];
            ulonglong2 sip = *(const ulonglong2*)&Si[ff][jc << 2];
#pragma unroll
            for (int u = 0; u < 4; ++u) {
                float2 cs = tw[nr + 16 * u][ff];
                ull cc = pack2(cs.x, cs.x);
                ull sn = pack2(cs.y, cs.y);
                ffma2(acc[u][0], cc, srp.x);
                ffma2(acc[u][0], sn, sip.x);
                ffma2(acc[u][1], cc, srp.y);
                ffma2(acc[u][1], sn, sip.y);
            }
        }
        __syncthreads();
    }
#pragma unroll
    for (int u = 0; u < 4; ++u) {
        int n = nr + 16 * u;
        if (n < M) {
            ulonglong2 st; st.x = acc[u][0]; st.y = acc[u][1];
            *(ulonglong2*)&out[(size_t)n * 64 + (jc << 2)] = st;
        }
    }
}

// ---------------- fused t0 + reconstruction for levels 12..6 -------------------
__global__ void k_deeprec(const float* __restrict__ t0w, const float* __restrict__ t0b) {
    extern __shared__ float dsm[];
    int b = blockIdx.x;
    int t = threadIdx.x;
    float* bufs0 = dsm;
    float* bufs1 = dsm + 8192;
    if (t < 16) {
        const float* row = g_sbuf + ((size_t)b * STRIDE_R + 8190) * 64 + t * 4;
        float in[4] = {row[0], row[1], row[2], row[3]};
#pragma unroll
        for (int kk = 0; kk < 4; ++kk) {
            float o = t0b[kk];
#pragma unroll
            for (int j = 0; j < 4; ++j) o += in[j] * t0w[kk * 4 + j];
            bufs0[t * 4 + kk] = o;
        }
    }
    __syncthreads();
    int parity = 0;
    for (int lev = 12; lev >= 6; --lev) {
        float* cur = parity ? bufs1 : bufs0;
        float* nxt = parity ? bufs0 : bufs1;
        int M = 4096 >> lev;
        int off = NFULL - (NFULL >> lev);
        int nu = M * 16;
#pragma unroll 1
        for (int q = t; q < nu; q += 256) {
            int c = q & 15, m = q >> 4;
            size_t grow = ((size_t)b * STRIDE_R + off + m) * 64 + c * 4;
            const float* us = &g_Us[grow];
            const float* ud = &g_Ud[grow];
            const float* xr = &cur[m * 64 + c * 4];
            float a[8] = {xr[0] + us[0], xr[1] + us[1], xr[2] + us[2], xr[3] + us[3],
                          ud[0], ud[1], ud[2], ud[3]};
            float e4[4] = {0, 0, 0, 0}, o4[4] = {0, 0, 0, 0};
#pragma unroll
            for (int r = 0; r < 8; ++r)
#pragma unroll
                for (int kk = 0; kk < 4; ++kk) {
                    e4[kk] += a[r] * g_rce[r][kk];
                    o4[kk] += a[r] * g_rco[r][kk];
                }
            *(float4*)&nxt[(2 * m) * 64 + c * 4]     = make_float4(e4[0], e4[1], e4[2], e4[3]);
            *(float4*)&nxt[(2 * m + 1) * 64 + c * 4] = make_float4(o4[0], o4[1], o4[2], o4[3]);
        }
        __syncthreads();
        parity ^= 1;
    }
    float* fin = parity ? bufs1 : bufs0;
    float* dst = g_sbuf + ((size_t)b * STRIDE_R + 7936) * 64;
    for (int q = t; q < 128 * 16; q += 256) {
        int r = q >> 4, c4 = (q & 15) << 2;
        *(float4*)&dst[r * 64 + c4] = *(const float4*)&fin[r * 64 + c4];
    }
}

// ---------------- fused inverse-DFT + reconstruction (levels 5..0) -------------
__global__ void k_invrec(float* __restrict__ xout, int ooff, int ostride, int lev) {
    int M = NFULL >> (lev + 1);
    int off = NFULL - (NFULL >> lev);
    int tile = blockIdx.x;
    int b = blockIdx.y;
    const float4* ud4 = (const float4*)(g_UdhatL + (size_t)lev * SPEC);
    const float4* us4 = (const float4*)(g_UshatL + (size_t)lev * SPEC);
    const float* twc = g_twc + (size_t)off * 64;
    const float* tws = g_tws + (size_t)off * 64;
    int n0 = tile * 64;
    int t = threadIdx.x;
    int nr = t >> 4;
    int jc = t & 15;

    __shared__ float Ur[32][64], Ui[32][64], Vr[32][64], Vi[32][64];
    __shared__ float2 tw[64][32];

    ull accU[4][2], accV[4][2];
#pragma unroll
    for (int u = 0; u < 4; ++u) {
        accU[u][0] = accU[u][1] = 0ULL;
        accV[u][0] = accV[u][1] = 0ULL;
    }

    for (int fb = 0; fb < 64; fb += 32) {
        for (int q = t; q < 32 * 32; q += 256) {
            int ff = q >> 5, jp = (q & 31) << 1;
            size_t sidx = ((size_t)b * 64 + fb + ff) * 32 + (q & 31);
            float4 uv = ud4[sidx];
            float4 vv = us4[sidx];
            Ur[ff][jp] = uv.x; Ui[ff][jp] = uv.y;
            Ur[ff][jp + 1] = uv.z; Ui[ff][jp + 1] = uv.w;
            Vr[ff][jp] = vv.x; Vi[ff][jp] = vv.y;
            Vr[ff][jp + 1] = vv.z; Vi[ff][jp + 1] = vv.w;
        }
        for (int q = t; q < 2048; q += 256) {
            int nn = q & 63, ff = q >> 6;
            int n = n0 + nn;
            float c = twc[(fb + ff) * M + n];
            float s = tws[(fb + ff) * M + n];
            tw[nn][ff] = make_float2(c, -s);
        }
        __syncthreads();
        for (int ff = 0; ff < 32; ++ff) {
            ulonglong2 urp = *(const ulonglong2*)&Ur[ff][jc << 2];
            ulonglong2 uip = *(const ulonglong2*)&Ui[ff][jc << 2];
            ulonglong2 vrp = *(const ulonglong2*)&Vr[ff][jc << 2];
            ulonglong2 vip = *(const ulonglong2*)&Vi[ff][jc << 2];
#pragma unroll
            for (int u = 0; u < 4; ++u) {
                float2 cs = tw[nr + 16 * u][ff];
                ull cc = pack2(cs.x, cs.x);
                ull sn = pack2(cs.y, cs.y);
                ffma2(accU[u][0], cc, urp.x);
                ffma2(accU[u][0], sn, uip.x);
                ffma2(accU[u][1], cc, urp.y);
                ffma2(accU[u][1], sn, uip.y);
                ffma2(accV[u][0], cc, vrp.x);
                ffma2(accV[u][0], sn, vip.x);
                ffma2(accV[u][1], cc, vrp.y);
                ffma2(accV[u][1], sn, vip.y);
            }
        }
        __syncthreads();
    }
#pragma unroll
    for (int u = 0; u < 4; ++u) {
        int n = n0 + nr + 16 * u;
        float udv[4], usv[4];
        unpack2(accU[u][0], udv[0], udv[1]);
        unpack2(accU[u][1], udv[2], udv[3]);
        unpack2(accV[u][0], usv[0], usv[1]);
        unpack2(accV[u][1], usv[2], usv[3]);
        float4 xv = *(const float4*)&g_sbuf[((size_t)b * STRIDE_R + off + n) * 64 + (jc << 2)];
        float a[8] = {xv.x + usv[0], xv.y + usv[1], xv.z + usv[2], xv.w + usv[3],
                      udv[0], udv[1], udv[2], udv[3]};
        float e4[4] = {0, 0, 0, 0}, o4[4] = {0, 0, 0, 0};
#pragma unroll
        for (int r = 0; r < 8; ++r)
#pragma unroll
            for (int kk = 0; kk < 4; ++kk) {
                e4[kk] += a[r] * g_rce[r][kk];
                o4[kk] += a[r] * g_rco[r][kk];
            }
        size_t orow = ((size_t)b * ostride + ooff + 2 * n) * 64 + (jc << 2);
        *(float4*)&xout[orow]      = make_float4(e4[0], e4[1], e4[2], e4[3]);
        *(float4*)&xout[orow + 64] = make_float4(o4[0], o4[1], o4[2], o4[3]);
    }
}

// ---------------- host orchestration (single stream) ----------------
extern "C" void kernel_launch(void* const* d_in, const int* in_sizes, int n_in,
                              void* d_out, int out_size) {
    (void)in_sizes; (void)n_in; (void)out_size;
    const float* x_in = (const float*)d_in[0];
    const float* wAre = (const float*)d_in[1];
    const float* wAim = (const float*)d_in[2];
    const float* wBre = (const float*)d_in[3];
    const float* wBim = (const float*)d_in[4];
    const float* wCre = (const float*)d_in[5];
    const float* wCim = (const float*)d_in[6];
    const float* t0w  = (const float*)d_in[7];
    const float* t0b  = (const float*)d_in[8];
    float* out = (float*)d_out;

    float* sbuf;
    cudaGetSymbolAddress((void**)&sbuf, g_sbuf);

    init_filters<<<1, 1>>>();
    fill_tw<<<(TWTOT + 255) / 256, 256>>>();
    k_transpose_w<<<dim3(64, 6), 256>>>(wAre, wAim, wBre, wBim, wCre, wCim);

    // decomposition: levels 0..5 (s-only), 6..12 fused (s+d)
    for (int lev = 0; lev <= 5; ++lev) {
        int M = 4096 >> lev;
        int off = NFULL - (NFULL >> lev);
        int tot = BB * M * CC;
        if (lev == 0)
            k_decompose<<<(tot + 255) / 256, 256>>>(x_in, 0, NFULL, 0, M);
        else
            k_decompose<<<(tot + 255) / 256, 256>>>(sbuf, NFULL - (NFULL >> (lev - 1)),
                                                    STRIDE_R, off, M);
    }
    k_deepdec<<<BB, 256>>>();

    // batched spectral pipeline (reduce fused into mix; d fused into fwd)
    k_fwd_all<<<dim3(24, BB, 2), 256>>>(x_in);
    k_mix_all<<<dim3(NLEV * 64, 4), 256>>>();
    k_inv_deep<<<dim3(7, BB, 2), 256>>>();

    // reconstruction: t0 + levels 12..6 fused, then fused inv+recon for 5..0
    cudaFuncSetAttribute(k_deeprec, cudaFuncAttributeMaxDynamicSharedMemorySize, 65536);
    k_deeprec<<<BB, 256, 65536>>>(t0w, t0b);
    for (int lev = 5; lev >= 1; --lev) {
        int M = NFULL >> (lev + 1);
        k_invrec<<<dim3(M / 64, BB), 256>>>(sbuf, NFULL - (NFULL >> (lev - 1)), STRIDE_R, lev);
    }
    k_invrec<<<dim3(64, BB), 256>>>(out, 0, NFULL, 0);
}

// round 16
// speedup vs baseline: 1.0600x; 1.0600x over previous
#include <cuda_runtime.h>

#define BB 32
#define NFULL 8192
#define STRIDE_R (NFULL-1)          /* 8191 rows per batch */
#define CC 16
#define CKD 64
#define NLEV 13
#define SPEC (BB*64*CKD*2)          /* 524288 floats per level */
#define TWTOT (64*(NFULL-1))        /* 524224 */

typedef unsigned long long ull;

// ---------------- static device scratch ----------------
__device__ float g_sbuf[BB*STRIDE_R*CKD];
__device__ float g_dbuf[BB*STRIDE_R*CKD];
__device__ float g_Ud[BB*STRIDE_R*CKD];
__device__ float g_Us[BB*STRIDE_R*CKD];
__device__ float g_DhatL[NLEV*SPEC];
__device__ float g_ShatL[NLEV*SPEC];
__device__ float g_UdhatL[NLEV*SPEC];
__device__ float g_UshatL[NLEV*SPEC];
__device__ float g_partD[14*SPEC];
__device__ float g_partS[14*SPEC];
__device__ float g_twc[TWTOT];
__device__ float g_tws[TWTOT];
__device__ float g_wT[6][CKD*CKD*64];   // [which][f][i][o]
__device__ float g_ecs[8][4];
__device__ float g_ecd[8][4];
__device__ float g_rce[8][4];
__device__ float g_rco[8][4];

// ---------------- f32x2 helpers ----------------
__device__ __forceinline__ void ffma2(ull& d, ull a, ull b) {
    asm("fma.rn.f32x2 %0, %1, %2, %0;" : "+l"(d) : "l"(a), "l"(b));
}
__device__ __forceinline__ ull pack2(float lo, float hi) {
    ull r;
    asm("mov.b64 %0, {%1, %2};" : "=l"(r) : "f"(lo), "f"(hi));
    return r;
}
__device__ __forceinline__ void unpack2(ull v, float& lo, float& hi) {
    asm("mov.b64 {%0, %1}, %2;" : "=f"(lo), "=f"(hi) : "l"(v));
}

// ---------------- Alpert multiwavelet filter construction (k=4, legendre) ------
__device__ double dproj(const double* a, int la, const double* b, int lb, bool upper) {
    double prod[16];
    int n = la + lb - 1;
    for (int t = 0; t < n; ++t) prod[t] = 0.0;
    for (int i = 0; i < la; ++i)
        for (int j = 0; j < lb; ++j)
            prod[i + j] += a[i] * b[j];
    double s = 0.0;
    double ph = 1.0;
    for (int t = 0; t < n; ++t) {
        ph *= 0.5;                       // ph = 0.5^(t+1), exact
        double p = prod[t];
        if (fabs(p) < 1e-8) p = 0.0;
        double w = (upper ? (1.0 - ph) : ph) / (double)(t + 1);
        s += p * w;
    }
    return s;
}

__device__ __forceinline__ double dpv(const double* c, double x) {
    return c[0] + x * (c[1] + x * (c[2] + x * c[3]));
}

__global__ void init_filters() {
    if (blockIdx.x != 0 || threadIdx.x != 0) return;
    const double legp[4][4] = {
        { 1.0,  0.0, 0.0, 0.0},
        { 0.0,  1.0, 0.0, 0.0},
        {-0.5,  0.0, 1.5, 0.0},
        { 0.0, -1.5, 0.0, 2.5}
    };
    double phi[4][4], phi2[4][4];
    for (int ki = 0; ki < 4; ++ki) {
        for (int pass = 0; pass < 2; ++pass) {
            double a0 = -1.0, a1 = (pass == 0) ? 2.0 : 4.0;
            double r[8]; for (int j = 0; j < 8; ++j) r[j] = 0.0;
            r[0] = legp[ki][ki];
            int rd = 0;
            for (int i = ki - 1; i >= 0; --i) {
                double nr[8]; for (int j = 0; j < 8; ++j) nr[j] = 0.0;
                for (int j = 0; j <= rd; ++j) { nr[j] += r[j] * a0; nr[j + 1] += r[j] * a1; }
                nr[0] += legp[ki][i];
                ++rd;
                for (int j = 0; j < 8; ++j) r[j] = nr[j];
            }
            double sc = (pass == 0) ? sqrt(2.0 * ki + 1.0) : sqrt(2.0) * sqrt(2.0 * ki + 1.0);
            for (int j = 0; j < 4; ++j) {
                double v = (j <= ki) ? r[j] * sc : 0.0;
                if (pass == 0) phi[ki][j] = v; else phi2[ki][j] = v;
            }
        }
    }
    double psi1[4][4], psi2[4][4];
    for (int i = 0; i < 4; ++i) for (int j = 0; j < 4; ++j) { psi1[i][j] = 0.0; psi2[i][j] = 0.0; }
    for (int ki = 0; ki < 4; ++ki) {
        for (int t = 0; t < 4; ++t) psi1[ki][t] = phi2[ki][t];
        for (int i = 0; i < 4; ++i) {
            double p = dproj(phi2[ki], ki + 1, phi[i], i + 1, false);
            for (int t = 0; t < 4; ++t) { psi1[ki][t] -= p * phi[i][t]; psi2[ki][t] -= p * phi[i][t]; }
        }
        for (int j = 0; j < ki; ++j) {
            double p = dproj(phi2[ki], ki + 1, psi1[j], 4, false);
            for (int t = 0; t < 4; ++t) { psi1[ki][t] -= p * psi1[j][t]; psi2[ki][t] -= p * psi2[j][t]; }
        }
        double n1 = dproj(psi1[ki], 4, psi1[ki], 4, false);
        double n2 = dproj(psi2[ki], 4, psi2[ki], 4, true);
        double nrm = sqrt(n1 + n2);
        for (int t = 0; t < 4; ++t) { psi1[ki][t] /= nrm; psi2[ki][t] /= nrm; }
        for (int t = 0; t < 4; ++t) {
            if (fabs(psi1[ki][t]) < 1e-8) psi1[ki][t] = 0.0;
            if (fabs(psi2[ki][t]) < 1e-8) psi2[ki][t] = 0.0;
        }
    }
    const double xm[4] = {0.06943184420297371, 0.33000947820757187,
                          0.66999052179242813, 0.93056815579702623};
    const double wm[4] = {0.17392742256872692, 0.32607257743127305,
                          0.32607257743127305, 0.17392742256872692};
    double H0[4][4], H1[4][4], G0[4][4], G1[4][4];
    double s2 = sqrt(2.0);
    for (int ki = 0; ki < 4; ++ki) {
        for (int kp = 0; kp < 4; ++kp) {
            double h0 = 0, h1 = 0, g0 = 0, g1 = 0;
            for (int m = 0; m < 4; ++m) {
                double pb = dpv(phi[kp], xm[m]);
                h0 += wm[m] * dpv(phi[ki],  xm[m] * 0.5) * pb;
                g0 += wm[m] * dpv(psi1[ki], xm[m] * 0.5) * pb;
                h1 += wm[m] * dpv(phi[ki],  (xm[m] + 1.0) * 0.5) * pb;
                g1 += wm[m] * dpv(psi2[ki], (xm[m] + 1.0) * 0.5) * pb;
            }
            H0[ki][kp] = h0 / s2; H1[ki][kp] = h1 / s2;
            G0[ki][kp] = g0 / s2; G1[ki][kp] = g1 / s2;
        }
    }
    for (int i = 0; i < 4; ++i) for (int j = 0; j < 4; ++j) {
        if (fabs(H0[i][j]) < 1e-8) H0[i][j] = 0.0;
        if (fabs(H1[i][j]) < 1e-8) H1[i][j] = 0.0;
        if (fabs(G0[i][j]) < 1e-8) G0[i][j] = 0.0;
        if (fabs(G1[i][j]) < 1e-8) G1[i][j] = 0.0;
    }
    for (int r = 0; r < 4; ++r) for (int c = 0; c < 4; ++c) {
        g_ecs[r][c]     = (float)H0[c][r];
        g_ecs[r + 4][c] = (float)H1[c][r];
        g_ecd[r][c]     = (float)G0[c][r];
        g_ecd[r + 4][c] = (float)G1[c][r];
        g_rce[r][c]     = (float)H0[r][c];
        g_rce[r + 4][c] = (float)G0[r][c];
        g_rco[r][c]     = (float)H1[r][c];
        g_rco[r + 4][c] = (float)G1[r][c];
    }
}

// ---------------- twiddles: per level sections, cos/sin(2*pi*f*n/M) ------------
__global__ void fill_tw() {
    int idx = blockIdx.x * blockDim.x + threadIdx.x;
    if (idx >= TWTOT) return;
    int off = 0, M = 0;
    for (int lev = 0; lev < NLEV; ++lev) {
        M = NFULL >> (lev + 1);
        int sz = 64 * M;
        if (idx < off + sz) break;
        off += sz;
    }
    int loc = idx - off;
    int f = loc / M;
    int n = loc % M;
    int r = (int)(((long long)f * n) % M);
    float ang = 2.0f * (float)r / (float)M;
    float s, c;
    sincospif(ang, &s, &c);
    g_twc[idx] = c;
    g_tws[idx] = s;
}

// ---------------- weight transpose: w[i][o][f] -> wT[f][i][o] ----------------
__global__ void k_transpose_w(const float* __restrict__ a0, const float* __restrict__ a1,
                              const float* __restrict__ a2, const float* __restrict__ a3,
                              const float* __restrict__ a4, const float* __restrict__ a5) {
    int idx = blockIdx.x * blockDim.x + threadIdx.x;
    if (idx >= CKD * CKD * 64) return;
    int f = idx >> 12;
    int i = (idx >> 6) & 63;
    int o = idx & 63;
    int src = (i * 64 + o) * 64 + f;
    g_wT[0][idx] = a0[src];
    g_wT[1][idx] = a1[src];
    g_wT[2][idx] = a2[src];
    g_wT[3][idx] = a3[src];
    g_wT[4][idx] = a4[src];
    g_wT[5][idx] = a5[src];
}

// ---------------- wavelet decomposition (levels 0..5, sequential) --------------
__global__ void k_decompose(const float* __restrict__ xin, int xoff, int xstride,
                            int off, int M) {
    int idx = blockIdx.x * blockDim.x + threadIdx.x;
    int tot = BB * M * CC;
    if (idx >= tot) return;
    int c = idx & 15;
    int m = (idx >> 4) % M;
    int b = idx / (CC * M);
    const float4* xi = (const float4*)xin;
    size_t r0 = ((size_t)b * xstride + xoff + 2 * m) * CC + c;
    float4 e = xi[r0];
    float4 o = xi[r0 + CC];
    float a[8] = {e.x, e.y, e.z, e.w, o.x, o.y, o.z, o.w};
    float sv[4] = {0, 0, 0, 0}, dv[4] = {0, 0, 0, 0};
#pragma unroll
    for (int r = 0; r < 8; ++r) {
#pragma unroll
        for (int kk = 0; kk < 4; ++kk) {
            sv[kk] += a[r] * g_ecs[r][kk];
            dv[kk] += a[r] * g_ecd[r][kk];
        }
    }
    size_t wrow = ((size_t)b * STRIDE_R + off + m) * CC + c;
    ((float4*)g_sbuf)[wrow] = make_float4(sv[0], sv[1], sv[2], sv[3]);
    ((float4*)g_dbuf)[wrow] = make_float4(dv[0], dv[1], dv[2], dv[3]);
}

// ---------------- fused decomposition for levels 6..12 (smem chain) ------------
__global__ void k_deepdec() {
    int b = blockIdx.x;
    int t = threadIdx.x;
    __shared__ float cur[128 * 64];
    const float* src = g_sbuf + ((size_t)b * STRIDE_R + (NFULL - 256)) * 64;
    for (int q = t; q < 128 * 16; q += 256) {
        int r = q >> 4, c4 = (q & 15) << 2;
        *(float4*)&cur[r * 64 + c4] = *(const float4*)&src[r * 64 + c4];
    }
    __syncthreads();
    for (int lev = 6; lev < 13; ++lev) {
        int M = 4096 >> lev;
        int off = NFULL - (NFULL >> lev);
        int nu = M * 16;
        float4 sv[4]; int has[4] = {0, 0, 0, 0};
#pragma unroll
        for (int qi = 0; qi < 4; ++qi) {
            int q = t + qi * 256;
            if (q < nu) {
                int c = q & 15, m = q >> 4;
                const float* r0 = &cur[(2 * m) * 64 + c * 4];
                const float* r1 = &cur[(2 * m + 1) * 64 + c * 4];
                float a[8] = {r0[0], r0[1], r0[2], r0[3], r1[0], r1[1], r1[2], r1[3]};
                float s4[4] = {0, 0, 0, 0}, d4[4] = {0, 0, 0, 0};
#pragma unroll
                for (int r = 0; r < 8; ++r)
#pragma unroll
                    for (int kk = 0; kk < 4; ++kk) {
                        s4[kk] += a[r] * g_ecs[r][kk];
                        d4[kk] += a[r] * g_ecd[r][kk];
                    }
                size_t wrow = ((size_t)b * STRIDE_R + off + m) * 64 + c * 4;
                *(float4*)&g_sbuf[wrow] = make_float4(s4[0], s4[1], s4[2], s4[3]);
                *(float4*)&g_dbuf[wrow] = make_float4(d4[0], d4[1], d4[2], d4[3]);
                sv[qi] = make_float4(s4[0], s4[1], s4[2], s4[3]);
                has[qi] = 1;
            }
        }
        __syncthreads();
#pragma unroll
        for (int qi = 0; qi < 4; ++qi) {
            int q = t + qi * 256;
            if (has[qi]) {
                int c = q & 15, m = q >> 4;
                *(float4*)&cur[m * 64 + c * 4] = sv[qi];
            }
        }
        __syncthreads();
    }
}

// ---------------- forward truncated DFT, all levels in one launch --------------
__global__ void k_fwd_all() {
    int cu = blockIdx.x;
    int b = blockIdx.y;
    int which = blockIdx.z;
    int lev, ch;
    if (cu < 8)       { lev = 0; ch = cu; }
    else if (cu < 12) { lev = 1; ch = cu - 8; }
    else if (cu < 14) { lev = 2; ch = cu - 12; }
    else              { lev = cu - 11; ch = 0; }
    int M = 4096 >> lev;
    int off = NFULL - (NFULL >> lev);
    int l = M / 2 + 1; if (l > 64) l = 64;
    int nch = (lev == 0) ? 8 : (lev == 1) ? 4 : (lev == 2) ? 2 : 1;
    int chunk = M / nch;
    const float* src = (which ? g_sbuf : g_dbuf) + ((size_t)b * STRIDE_R + off) * 64;
    float* dst;
    if (nch == 1) {
        dst = (which ? g_ShatL : g_DhatL) + (size_t)lev * SPEC;
    } else {
        int ub = (lev == 0) ? 0 : (lev == 1) ? 8 : 12;
        dst = (which ? g_partS : g_partD) + (size_t)(ub + ch) * SPEC;
    }
    const float* twc = g_twc + (size_t)off * 64;
    const float* tws = g_tws + (size_t)off * 64;
    int n0 = ch * chunk;
    int n1 = n0 + chunk;
    int t = threadIdx.x;
    int fr = t >> 4;
    int jc = t & 15;

    __shared__ float xs[32][64];
    __shared__ ull tw[64][32];   // (c, -s)

    ull acc[4][4];
#pragma unroll
    for (int u = 0; u < 4; ++u)
#pragma unroll
        for (int v = 0; v < 4; ++v) acc[u][v] = 0ULL;

    for (int nb = n0; nb < n1; nb += 32) {
        int cnt = n1 - nb; if (cnt > 32) cnt = 32;
        for (int q = t; q < cnt * 16; q += 256) {
            int nn = q >> 4, jj = (q & 15) << 2;
            *(float4*)&xs[nn][jj] = *(const float4*)&src[(size_t)(nb + nn) * 64 + jj];
        }
        for (int q = t; q < 2048; q += 256) {
            int f = q >> 5, nn = q & 31;
            float c = 0.0f, s = 0.0f;
            if (nn < cnt) { c = twc[f * M + nb + nn]; s = tws[f * M + nb + nn]; }
            tw[f][nn] = pack2(c, -s);
        }
        __syncthreads();
        if (cnt == 32) {
#pragma unroll 2
            for (int nn = 0; nn < 32; ++nn) {
                float4 xv = *(const float4*)&xs[nn][jc << 2];
                ull xx0 = pack2(xv.x, xv.x);
                ull xx1 = pack2(xv.y, xv.y);
                ull xx2 = pack2(xv.z, xv.z);
                ull xx3 = pack2(xv.w, xv.w);
#pragma unroll
                for (int u = 0; u < 4; ++u) {
                    ull csp = tw[fr + 16 * u][nn];
                    ffma2(acc[u][0], csp, xx0);
                    ffma2(acc[u][1], csp, xx1);
                    ffma2(acc[u][2], csp, xx2);
                    ffma2(acc[u][3], csp, xx3);
                }
            }
        } else {
            for (int nn = 0; nn < cnt; ++nn) {
                float4 xv = *(const float4*)&xs[nn][jc << 2];
                ull xx0 = pack2(xv.x, xv.x);
                ull xx1 = pack2(xv.y, xv.y);
                ull xx2 = pack2(xv.z, xv.z);
                ull xx3 = pack2(xv.w, xv.w);
#pragma unroll
                for (int u = 0; u < 4; ++u) {
                    ull csp = tw[fr + 16 * u][nn];
                    ffma2(acc[u][0], csp, xx0);
                    ffma2(acc[u][1], csp, xx1);
                    ffma2(acc[u][2], csp, xx2);
                    ffma2(acc[u][3], csp, xx3);
                }
            }
        }
        __syncthreads();
    }
#pragma unroll
    for (int u = 0; u < 4; ++u) {
        int f = fr + 16 * u;
        if (f < l) {
            size_t base = ((((size_t)b * 64 + f) * 64) + (jc << 2)) * 2;
            ulonglong2 s0; s0.x = acc[u][0]; s0.y = acc[u][1];
            ulonglong2 s1; s1.x = acc[u][2]; s1.y = acc[u][3];
            *(ulonglong2*)&dst[base]     = s0;
            *(ulonglong2*)&dst[base + 4] = s1;
        }
    }
}

// ---------------- per-mode complex mixing, all levels ----------------
// Chunk-partial reduction for levels 0..2 fused into the staging loop.
__global__ void k_mix_all() {
    int lev = blockIdx.x >> 6;
    int f = blockIdx.x & 63;
    int M = 4096 >> lev;
    int l = M / 2 + 1; if (l > 64) l = 64;
    if (f >= l) return;
    int b0 = blockIdx.y * 8;
    int t = threadIdx.x;
    const float2* D2 = (const float2*)(g_DhatL + (size_t)lev * SPEC);
    const float2* S2 = (const float2*)(g_ShatL + (size_t)lev * SPEC);
    __shared__ ull Dp[8][64], Dn[8][64], Sp[8][64], Sn[8][64];
    __shared__ float wsm[6][16][64];
    for (int q = t; q < 8 * 64; q += 256) {
        int bb = q >> 6, i = q & 63;
        size_t base = ((size_t)(b0 + bb) * 64 + f) * 64 + i;
        float2 dv, sv;
        if (lev < 3) {
            int nch = (lev == 0) ? 8 : (lev == 1) ? 4 : 2;
            int ub  = (lev == 0) ? 0 : (lev == 1) ? 8 : 12;
            float dr = 0.0f, di = 0.0f, sr = 0.0f, si = 0.0f;
            for (int c = 0; c < nch; ++c) {
                const float2* Pd = (const float2*)(g_partD + (size_t)(ub + c) * SPEC);
                const float2* Ps = (const float2*)(g_partS + (size_t)(ub + c) * SPEC);
                float2 a = Pd[base];
                float2 e = Ps[base];
                dr += a.x; di += a.y;
                sr += e.x; si += e.y;
            }
            dv = make_float2(dr, di);
            sv = make_float2(sr, si);
        } else {
            dv = D2[base];
            sv = S2[base];
        }
        Dp[bb][i] = pack2(dv.x, dv.y);
        Dn[bb][i] = pack2(-dv.y, dv.x);
        Sp[bb][i] = pack2(sv.x, sv.y);
        Sn[bb][i] = pack2(-sv.y, sv.x);
    }
    int o = t & 63;
    int bs = t >> 6;
    ull ud[2] = {0ULL, 0ULL}, us[2] = {0ULL, 0ULL};
    for (int ib = 0; ib < 64; ib += 16) {
        __syncthreads();
        for (int q = t; q < 16 * 64; q += 256) {
            int ii = q >> 6, oo = q & 63;
            int gi = f * 4096 + (ib + ii) * 64 + oo;
#pragma unroll
            for (int w = 0; w < 6; ++w) wsm[w][ii][oo] = g_wT[w][gi];
        }
        __syncthreads();
#pragma unroll 4
        for (int ii = 0; ii < 16; ++ii) {
            int i = ib + ii;
            float war = wsm[0][ii][o], wai = wsm[1][ii][o];
            float wbr = wsm[2][ii][o], wbi = wsm[3][ii][o];
            float wcr = wsm[4][ii][o], wci = wsm[5][ii][o];
            ull arr = pack2(war, war), aii = pack2(wai, wai);
            ull brr = pack2(wbr, wbr), bii = pack2(wbi, wbi);
            ull crr = pack2(wcr, wcr), cii = pack2(wci, wci);
#pragma unroll
            for (int q = 0; q < 2; ++q) {
                int bb = bs + 4 * q;
                ull dp = Dp[bb][i], dn = Dn[bb][i];
                ull sp = Sp[bb][i], sn = Sn[bb][i];
                ffma2(ud[q], arr, dp);
                ffma2(ud[q], aii, dn);
                ffma2(ud[q], brr, sp);
                ffma2(ud[q], bii, sn);
                ffma2(us[q], crr, dp);
                ffma2(us[q], cii, dn);
            }
        }
    }
    float alpha = (f == 0 || 2 * f == M) ? 1.0f : 2.0f;
    float sc = alpha / (float)M;
    float2* U2 = (float2*)(g_UdhatL + (size_t)lev * SPEC);
    float2* V2 = (float2*)(g_UshatL + (size_t)lev * SPEC);
#pragma unroll
    for (int q = 0; q < 2; ++q) {
        int b = b0 + bs + 4 * q;
        size_t base = ((size_t)b * 64 + f) * 64 + o;
        float ur, uv, vr, vv;
        unpack2(ud[q], ur, uv);
        unpack2(us[q], vr, vv);
        U2[base] = make_float2(ur * sc, uv * sc);
        V2[base] = make_float2(vr * sc, vv * sc);
    }
}

// ---------------- inverse DFT for deep levels 6..12 only -----------------------
__global__ void k_inv_deep() {
    int lev = 6 + blockIdx.x;
    int b = blockIdx.y;
    int which = blockIdx.z;
    int M = 4096 >> lev;
    int off = NFULL - (NFULL >> lev);
    int l = M / 2 + 1; if (l > 64) l = 64;
    const float4* spec4 = (const float4*)((which ? g_UshatL : g_UdhatL) + (size_t)lev * SPEC);
    float* out = (which ? g_Us : g_Ud) + ((size_t)b * STRIDE_R + off) * 64;
    const float* twc = g_twc + (size_t)off * 64;
    const float* tws = g_tws + (size_t)off * 64;
    int t = threadIdx.x;
    int nr = t >> 4;
    int jc = t & 15;

    __shared__ float Sr[32][64], Si[32][64];
    __shared__ float2 tw[64][32];

    ull acc[4][2];
#pragma unroll
    for (int u = 0; u < 4; ++u) { acc[u][0] = 0ULL; acc[u][1] = 0ULL; }

    for (int fb = 0; fb < l; fb += 32) {
        int cnt = l - fb; if (cnt > 32) cnt = 32;
        for (int q = t; q < cnt * 32; q += 256) {
            int ff = q >> 5, jp = (q & 31) << 1;
            float4 sv = spec4[((size_t)b * 64 + fb + ff) * 32 + (q & 31)];
            Sr[ff][jp] = sv.x; Si[ff][jp] = sv.y;
            Sr[ff][jp + 1] = sv.z; Si[ff][jp + 1] = sv.w;
        }
        for (int q = t; q < 2048; q += 256) {
            int nn = q & 63, ff = q >> 6;
            float c = 0.0f, s = 0.0f;
            if (ff < cnt && nn < M) { c = twc[(fb + ff) * M + nn]; s = tws[(fb + ff) * M + nn]; }
            tw[nn][ff] = make_float2(c, -s);
        }
        __syncthreads();
        for (int ff = 0; ff < cnt; ++ff) {
            ulonglong2 srp = *(const ulonglong2*)&Sr[ff][jc << 2];
            ulonglong2 sip = *(const ulonglong2*)&Si[ff][jc << 2];
#pragma unroll
            for (int u = 0; u < 4; ++u) {
                float2 cs = tw[nr + 16 * u][ff];
                ull cc = pack2(cs.x, cs.x);
                ull sn = pack2(cs.y, cs.y);
                ffma2(acc[u][0], cc, srp.x);
                ffma2(acc[u][0], sn, sip.x);
                ffma2(acc[u][1], cc, srp.y);
                ffma2(acc[u][1], sn, sip.y);
            }
        }
        __syncthreads();
    }
#pragma unroll
    for (int u = 0; u < 4; ++u) {
        int n = nr + 16 * u;
        if (n < M) {
            ulonglong2 st; st.x = acc[u][0]; st.y = acc[u][1];
            *(ulonglong2*)&out[(size_t)n * 64 + (jc << 2)] = st;
        }
    }
}

// ---------------- fused t0 + reconstruction for levels 12..6 -------------------
__global__ void k_deeprec(const float* __restrict__ t0w, const float* __restrict__ t0b) {
    extern __shared__ float dsm[];
    int b = blockIdx.x;
    int t = threadIdx.x;
    float* bufs0 = dsm;
    float* bufs1 = dsm + 8192;
    if (t < 16) {
        const float* row = g_sbuf + ((size_t)b * STRIDE_R + 8190) * 64 + t * 4;
        float in[4] = {row[0], row[1], row[2], row[3]};
#pragma unroll
        for (int kk = 0; kk < 4; ++kk) {
            float o = t0b[kk];
#pragma unroll
            for (int j = 0; j < 4; ++j) o += in[j] * t0w[kk * 4 + j];
            bufs0[t * 4 + kk] = o;
        }
    }
    __syncthreads();
    int parity = 0;
    for (int lev = 12; lev >= 6; --lev) {
        float* cur = parity ? bufs1 : bufs0;
        float* nxt = parity ? bufs0 : bufs1;
        int M = 4096 >> lev;
        int off = NFULL - (NFULL >> lev);
        int nu = M * 16;
#pragma unroll 1
        for (int q = t; q < nu; q += 256) {
            int c = q & 15, m = q >> 4;
            size_t grow = ((size_t)b * STRIDE_R + off + m) * 64 + c * 4;
            const float* us = &g_Us[grow];
            const float* ud = &g_Ud[grow];
            const float* xr = &cur[m * 64 + c * 4];
            float a[8] = {xr[0] + us[0], xr[1] + us[1], xr[2] + us[2], xr[3] + us[3],
                          ud[0], ud[1], ud[2], ud[3]};
            float e4[4] = {0, 0, 0, 0}, o4[4] = {0, 0, 0, 0};
#pragma unroll
            for (int r = 0; r < 8; ++r)
#pragma unroll
                for (int kk = 0; kk < 4; ++kk) {
                    e4[kk] += a[r] * g_rce[r][kk];
                    o4[kk] += a[r] * g_rco[r][kk];
                }
            *(float4*)&nxt[(2 * m) * 64 + c * 4]     = make_float4(e4[0], e4[1], e4[2], e4[3]);
            *(float4*)&nxt[(2 * m + 1) * 64 + c * 4] = make_float4(o4[0], o4[1], o4[2], o4[3]);
        }
        __syncthreads();
        parity ^= 1;
    }
    float* fin = parity ? bufs1 : bufs0;
    float* dst = g_sbuf + ((size_t)b * STRIDE_R + 7936) * 64;
    for (int q = t; q < 128 * 16; q += 256) {
        int r = q >> 4, c4 = (q & 15) << 2;
        *(float4*)&dst[r * 64 + c4] = *(const float4*)&fin[r * 64 + c4];
    }
}

// ---------------- fused inverse-DFT + reconstruction (levels 5..0) -------------
__global__ void k_invrec(float* __restrict__ xout, int ooff, int ostride, int lev) {
    int M = NFULL >> (lev + 1);
    int off = NFULL - (NFULL >> lev);
    int tile = blockIdx.x;
    int b = blockIdx.y;
    const float4* ud4 = (const float4*)(g_UdhatL + (size_t)lev * SPEC);
    const float4* us4 = (const float4*)(g_UshatL + (size_t)lev * SPEC);
    const float* twc = g_twc + (size_t)off * 64;
    const float* tws = g_tws + (size_t)off * 64;
    int n0 = tile * 64;
    int t = threadIdx.x;
    int nr = t >> 4;
    int jc = t & 15;

    __shared__ float Ur[32][64], Ui[32][64], Vr[32][64], Vi[32][64];
    __shared__ float2 tw[64][32];

    ull accU[4][2], accV[4][2];
#pragma unroll
    for (int u = 0; u < 4; ++u) {
        accU[u][0] = accU[u][1] = 0ULL;
        accV[u][0] = accV[u][1] = 0ULL;
    }

    for (int fb = 0; fb < 64; fb += 32) {
        for (int q = t; q < 32 * 32; q += 256) {
            int ff = q >> 5, jp = (q & 31) << 1;
            size_t sidx = ((size_t)b * 64 + fb + ff) * 32 + (q & 31);
            float4 uv = ud4[sidx];
            float4 vv = us4[sidx];
            Ur[ff][jp] = uv.x; Ui[ff][jp] = uv.y;
            Ur[ff][jp + 1] = uv.z; Ui[ff][jp + 1] = uv.w;
            Vr[ff][jp] = vv.x; Vi[ff][jp] = vv.y;
            Vr[ff][jp + 1] = vv.z; Vi[ff][jp + 1] = vv.w;
        }
        for (int q = t; q < 2048; q += 256) {
            int nn = q & 63, ff = q >> 6;
            int n = n0 + nn;
            float c = twc[(fb + ff) * M + n];
            float s = tws[(fb + ff) * M + n];
            tw[nn][ff] = make_float2(c, -s);
        }
        __syncthreads();
        for (int ff = 0; ff < 32; ++ff) {
            ulonglong2 urp = *(const ulonglong2*)&Ur[ff][jc << 2];
            ulonglong2 uip = *(const ulonglong2*)&Ui[ff][jc << 2];
            ulonglong2 vrp = *(const ulonglong2*)&Vr[ff][jc << 2];
            ulonglong2 vip = *(const ulonglong2*)&Vi[ff][jc << 2];
#pragma unroll
            for (int u = 0; u < 4; ++u) {
                float2 cs = tw[nr + 16 * u][ff];
                ull cc = pack2(cs.x, cs.x);
                ull sn = pack2(cs.y, cs.y);
                ffma2(accU[u][0], cc, urp.x);
                ffma2(accU[u][0], sn, uip.x);
                ffma2(accU[u][1], cc, urp.y);
                ffma2(accU[u][1], sn, uip.y);
                ffma2(accV[u][0], cc, vrp.x);
                ffma2(accV[u][0], sn, vip.x);
                ffma2(accV[u][1], cc, vrp.y);
                ffma2(accV[u][1], sn, vip.y);
            }
        }
        __syncthreads();
    }
#pragma unroll
    for (int u = 0; u < 4; ++u) {
        int n = n0 + nr + 16 * u;
        float udv[4], usv[4];
        unpack2(accU[u][0], udv[0], udv[1]);
        unpack2(accU[u][1], udv[2], udv[3]);
        unpack2(accV[u][0], usv[0], usv[1]);
        unpack2(accV[u][1], usv[2], usv[3]);
        float4 xv = *(const float4*)&g_sbuf[((size_t)b * STRIDE_R + off + n) * 64 + (jc << 2)];
        float a[8] = {xv.x + usv[0], xv.y + usv[1], xv.z + usv[2], xv.w + usv[3],
                      udv[0], udv[1], udv[2], udv[3]};
        float e4[4] = {0, 0, 0, 0}, o4[4] = {0, 0, 0, 0};
#pragma unroll
        for (int r = 0; r < 8; ++r)
#pragma unroll
            for (int kk = 0; kk < 4; ++kk) {
                e4[kk] += a[r] * g_rce[r][kk];
                o4[kk] += a[r] * g_rco[r][kk];
            }
        size_t orow = ((size_t)b * ostride + ooff + 2 * n) * 64 + (jc << 2);
        *(float4*)&xout[orow]      = make_float4(e4[0], e4[1], e4[2], e4[3]);
        *(float4*)&xout[orow + 64] = make_float4(o4[0], o4[1], o4[2], o4[3]);
    }
}

// ---------------- host orchestration (single stream) ----------------
extern "C" void kernel_launch(void* const* d_in, const int* in_sizes, int n_in,
                              void* d_out, int out_size) {
    (void)in_sizes; (void)n_in; (void)out_size;
    const float* x_in = (const float*)d_in[0];
    const float* wAre = (const float*)d_in[1];
    const float* wAim = (const float*)d_in[2];
    const float* wBre = (const float*)d_in[3];
    const float* wBim = (const float*)d_in[4];
    const float* wCre = (const float*)d_in[5];
    const float* wCim = (const float*)d_in[6];
    const float* t0w  = (const float*)d_in[7];
    const float* t0b  = (const float*)d_in[8];
    float* out = (float*)d_out;

    float* sbuf;
    cudaGetSymbolAddress((void**)&sbuf, g_sbuf);

    init_filters<<<1, 1>>>();
    fill_tw<<<(TWTOT + 255) / 256, 256>>>();
    k_transpose_w<<<(CKD * CKD * 64 + 255) / 256, 256>>>(wAre, wAim, wBre, wBim, wCre, wCim);

    // decomposition: levels 0..5 sequential, 6..12 fused
    for (int lev = 0; lev <= 5; ++lev) {
        int M = 4096 >> lev;
        int off = NFULL - (NFULL >> lev);
        int tot = BB * M * CC;
        if (lev == 0)
            k_decompose<<<(tot + 255) / 256, 256>>>(x_in, 0, NFULL, 0, M);
        else
            k_decompose<<<(tot + 255) / 256, 256>>>(sbuf, NFULL - (NFULL >> (lev - 1)),
                                                    STRIDE_R, off, M);
    }
    k_deepdec<<<BB, 256>>>();

    // batched spectral pipeline (reduce fused into mix)
    k_fwd_all<<<dim3(24, BB, 2), 256>>>();
    k_mix_all<<<dim3(NLEV * 64, 4), 256>>>();
    k_inv_deep<<<dim3(7, BB, 2), 256>>>();

    // reconstruction: t0 + levels 12..6 fused, then fused inv+recon for 5..0
    cudaFuncSetAttribute(k_deeprec, cudaFuncAttributeMaxDynamicSharedMemorySize, 65536);
    k_deeprec<<<BB, 256, 65536>>>(t0w, t0b);
    for (int lev = 5; lev >= 1; --lev) {
        int M = NFULL >> (lev + 1);
        k_invrec<<<dim3(M / 64, BB), 256>>>(sbuf, NFULL - (NFULL >> (lev - 1)), STRIDE_R, lev);
    }
    k_invrec<<<dim3(64, BB), 256>>>(out, 0, NFULL, 0);
}

// round 17
// speedup vs baseline: 1.0686x; 1.0081x over previous
#include <cuda_runtime.h>

#define BB 32
#define NFULL 8192
#define STRIDE_R (NFULL-1)          /* 8191 rows per batch */
#define CC 16
#define CKD 64
#define NLEV 13
#define SPEC (BB*64*CKD*2)          /* 524288 floats per level */
#define TWTOT (64*(NFULL-1))        /* 524224 */

typedef unsigned long long ull;

// ---------------- static device scratch ----------------
__device__ float g_sbuf[BB*STRIDE_R*CKD];
__device__ float g_dbuf[BB*STRIDE_R*CKD];
__device__ float g_Ud[BB*STRIDE_R*CKD];
__device__ float g_Us[BB*STRIDE_R*CKD];
__device__ float g_DhatL[NLEV*SPEC];
__device__ float g_ShatL[NLEV*SPEC];
__device__ float g_UdhatL[NLEV*SPEC];
__device__ float g_UshatL[NLEV*SPEC];
__device__ float g_partD[30*SPEC];
__device__ float g_partS[30*SPEC];
__device__ float g_twc[TWTOT];
__device__ float g_tws[TWTOT];
__device__ float g_wT[6][CKD*CKD*64];   // [which][f][i][o]
__device__ float g_ecs[8][4];
__device__ float g_ecd[8][4];
__device__ float g_rce[8][4];
__device__ float g_rco[8][4];

// ---------------- f32x2 helpers ----------------
__device__ __forceinline__ void ffma2(ull& d, ull a, ull b) {
    asm("fma.rn.f32x2 %0, %1, %2, %0;" : "+l"(d) : "l"(a), "l"(b));
}
__device__ __forceinline__ ull pack2(float lo, float hi) {
    ull r;
    asm("mov.b64 %0, {%1, %2};" : "=l"(r) : "f"(lo), "f"(hi));
    return r;
}
__device__ __forceinline__ void unpack2(ull v, float& lo, float& hi) {
    asm("mov.b64 {%0, %1}, %2;" : "=f"(lo), "=f"(hi) : "l"(v));
}

// ---------------- Alpert multiwavelet filter construction (k=4, legendre) ------
__device__ double dproj(const double* a, int la, const double* b, int lb, bool upper) {
    double prod[16];
    int n = la + lb - 1;
    for (int t = 0; t < n; ++t) prod[t] = 0.0;
    for (int i = 0; i < la; ++i)
        for (int j = 0; j < lb; ++j)
            prod[i + j] += a[i] * b[j];
    double s = 0.0;
    double ph = 1.0;
    for (int t = 0; t < n; ++t) {
        ph *= 0.5;                       // ph = 0.5^(t+1), exact
        double p = prod[t];
        if (fabs(p) < 1e-8) p = 0.0;
        double w = (upper ? (1.0 - ph) : ph) / (double)(t + 1);
        s += p * w;
    }
    return s;
}

__device__ __forceinline__ double dpv(const double* c, double x) {
    return c[0] + x * (c[1] + x * (c[2] + x * c[3]));
}

__global__ void init_filters() {
    if (blockIdx.x != 0 || threadIdx.x != 0) return;
    const double legp[4][4] = {
        { 1.0,  0.0, 0.0, 0.0},
        { 0.0,  1.0, 0.0, 0.0},
        {-0.5,  0.0, 1.5, 0.0},
        { 0.0, -1.5, 0.0, 2.5}
    };
    double phi[4][4], phi2[4][4];
    for (int ki = 0; ki < 4; ++ki) {
        for (int pass = 0; pass < 2; ++pass) {
            double a0 = -1.0, a1 = (pass == 0) ? 2.0 : 4.0;
            double r[8]; for (int j = 0; j < 8; ++j) r[j] = 0.0;
            r[0] = legp[ki][ki];
            int rd = 0;
            for (int i = ki - 1; i >= 0; --i) {
                double nr[8]; for (int j = 0; j < 8; ++j) nr[j] = 0.0;
                for (int j = 0; j <= rd; ++j) { nr[j] += r[j] * a0; nr[j + 1] += r[j] * a1; }
                nr[0] += legp[ki][i];
                ++rd;
                for (int j = 0; j < 8; ++j) r[j] = nr[j];
            }
            double sc = (pass == 0) ? sqrt(2.0 * ki + 1.0) : sqrt(2.0) * sqrt(2.0 * ki + 1.0);
            for (int j = 0; j < 4; ++j) {
                double v = (j <= ki) ? r[j] * sc : 0.0;
                if (pass == 0) phi[ki][j] = v; else phi2[ki][j] = v;
            }
        }
    }
    double psi1[4][4], psi2[4][4];
    for (int i = 0; i < 4; ++i) for (int j = 0; j < 4; ++j) { psi1[i][j] = 0.0; psi2[i][j] = 0.0; }
    for (int ki = 0; ki < 4; ++ki) {
        for (int t = 0; t < 4; ++t) psi1[ki][t] = phi2[ki][t];
        for (int i = 0; i < 4; ++i) {
            double p = dproj(phi2[ki], ki + 1, phi[i], i + 1, false);
            for (int t = 0; t < 4; ++t) { psi1[ki][t] -= p * phi[i][t]; psi2[ki][t] -= p * phi[i][t]; }
        }
        for (int j = 0; j < ki; ++j) {
            double p = dproj(phi2[ki], ki + 1, psi1[j], 4, false);
            for (int t = 0; t < 4; ++t) { psi1[ki][t] -= p * psi1[j][t]; psi2[ki][t] -= p * psi2[j][t]; }
        }
        double n1 = dproj(psi1[ki], 4, psi1[ki], 4, false);
        double n2 = dproj(psi2[ki], 4, psi2[ki], 4, true);
        double nrm = sqrt(n1 + n2);
        for (int t = 0; t < 4; ++t) { psi1[ki][t] /= nrm; psi2[ki][t] /= nrm; }
        for (int t = 0; t < 4; ++t) {
            if (fabs(psi1[ki][t]) < 1e-8) psi1[ki][t] = 0.0;
            if (fabs(psi2[ki][t]) < 1e-8) psi2[ki][t] = 0.0;
        }
    }
    const double xm[4] = {0.06943184420297371, 0.33000947820757187,
                          0.66999052179242813, 0.93056815579702623};
    const double wm[4] = {0.17392742256872692, 0.32607257743127305,
                          0.32607257743127305, 0.17392742256872692};
    double H0[4][4], H1[4][4], G0[4][4], G1[4][4];
    double s2 = sqrt(2.0);
    for (int ki = 0; ki < 4; ++ki) {
        for (int kp = 0; kp < 4; ++kp) {
            double h0 = 0, h1 = 0, g0 = 0, g1 = 0;
            for (int m = 0; m < 4; ++m) {
                double pb = dpv(phi[kp], xm[m]);
                h0 += wm[m] * dpv(phi[ki],  xm[m] * 0.5) * pb;
                g0 += wm[m] * dpv(psi1[ki], xm[m] * 0.5) * pb;
                h1 += wm[m] * dpv(phi[ki],  (xm[m] + 1.0) * 0.5) * pb;
                g1 += wm[m] * dpv(psi2[ki], (xm[m] + 1.0) * 0.5) * pb;
            }
            H0[ki][kp] = h0 / s2; H1[ki][kp] = h1 / s2;
            G0[ki][kp] = g0 / s2; G1[ki][kp] = g1 / s2;
        }
    }
    for (int i = 0; i < 4; ++i) for (int j = 0; j < 4; ++j) {
        if (fabs(H0[i][j]) < 1e-8) H0[i][j] = 0.0;
        if (fabs(H1[i][j]) < 1e-8) H1[i][j] = 0.0;
        if (fabs(G0[i][j]) < 1e-8) G0[i][j] = 0.0;
        if (fabs(G1[i][j]) < 1e-8) G1[i][j] = 0.0;
    }
    for (int r = 0; r < 4; ++r) for (int c = 0; c < 4; ++c) {
        g_ecs[r][c]     = (float)H0[c][r];
        g_ecs[r + 4][c] = (float)H1[c][r];
        g_ecd[r][c]     = (float)G0[c][r];
        g_ecd[r + 4][c] = (float)G1[c][r];
        g_rce[r][c]     = (float)H0[r][c];
        g_rce[r + 4][c] = (float)G0[r][c];
        g_rco[r][c]     = (float)H1[r][c];
        g_rco[r + 4][c] = (float)G1[r][c];
    }
}

// ---------------- twiddles: per level sections, cos/sin(2*pi*f*n/M) ------------
__global__ void fill_tw() {
    int idx = blockIdx.x * blockDim.x + threadIdx.x;
    if (idx >= TWTOT) return;
    int off = 0, M = 0;
    for (int lev = 0; lev < NLEV; ++lev) {
        M = NFULL >> (lev + 1);
        int sz = 64 * M;
        if (idx < off + sz) break;
        off += sz;
    }
    int loc = idx - off;
    int f = loc / M;
    int n = loc % M;
    int r = (int)(((long long)f * n) % M);
    float ang = 2.0f * (float)r / (float)M;
    float s, c;
    sincospif(ang, &s, &c);
    g_twc[idx] = c;
    g_tws[idx] = s;
}

// ---------------- weight transpose: w[i][o][f] -> wT[f][i][o] ----------------
__global__ void k_transpose_w(const float* __restrict__ a0, const float* __restrict__ a1,
                              const float* __restrict__ a2, const float* __restrict__ a3,
                              const float* __restrict__ a4, const float* __restrict__ a5) {
    int idx = blockIdx.x * blockDim.x + threadIdx.x;
    if (idx >= CKD * CKD * 64) return;
    int f = idx >> 12;
    int i = (idx >> 6) & 63;
    int o = idx & 63;
    int src = (i * 64 + o) * 64 + f;
    g_wT[0][idx] = a0[src];
    g_wT[1][idx] = a1[src];
    g_wT[2][idx] = a2[src];
    g_wT[3][idx] = a3[src];
    g_wT[4][idx] = a4[src];
    g_wT[5][idx] = a5[src];
}

// ---------------- wavelet decomposition (levels 0..5, sequential) --------------
__global__ void k_decompose(const float* __restrict__ xin, int xoff, int xstride,
                            int off, int M) {
    int idx = blockIdx.x * blockDim.x + threadIdx.x;
    int tot = BB * M * CC;
    if (idx >= tot) return;
    int c = idx & 15;
    int m = (idx >> 4) % M;
    int b = idx / (CC * M);
    const float4* xi = (const float4*)xin;
    size_t r0 = ((size_t)b * xstride + xoff + 2 * m) * CC + c;
    float4 e = xi[r0];
    float4 o = xi[r0 + CC];
    float a[8] = {e.x, e.y, e.z, e.w, o.x, o.y, o.z, o.w};
    float sv[4] = {0, 0, 0, 0}, dv[4] = {0, 0, 0, 0};
#pragma unroll
    for (int r = 0; r < 8; ++r) {
#pragma unroll
        for (int kk = 0; kk < 4; ++kk) {
            sv[kk] += a[r] * g_ecs[r][kk];
            dv[kk] += a[r] * g_ecd[r][kk];
        }
    }
    size_t wrow = ((size_t)b * STRIDE_R + off + m) * CC + c;
    ((float4*)g_sbuf)[wrow] = make_float4(sv[0], sv[1], sv[2], sv[3]);
    ((float4*)g_dbuf)[wrow] = make_float4(dv[0], dv[1], dv[2], dv[3]);
}

// ---------------- fused decomposition for levels 6..12 (smem chain) ------------
__global__ void k_deepdec() {
    int b = blockIdx.x;
    int t = threadIdx.x;
    __shared__ float cur[128 * 64];
    const float* src = g_sbuf + ((size_t)b * STRIDE_R + (NFULL - 256)) * 64;
    for (int q = t; q < 128 * 16; q += 256) {
        int r = q >> 4, c4 = (q & 15) << 2;
        *(float4*)&cur[r * 64 + c4] = *(const float4*)&src[r * 64 + c4];
    }
    __syncthreads();
    for (int lev = 6; lev < 13; ++lev) {
        int M = 4096 >> lev;
        int off = NFULL - (NFULL >> lev);
        int nu = M * 16;
        float4 sv[4]; int has[4] = {0, 0, 0, 0};
#pragma unroll
        for (int qi = 0; qi < 4; ++qi) {
            int q = t + qi * 256;
            if (q < nu) {
                int c = q & 15, m = q >> 4;
                const float* r0 = &cur[(2 * m) * 64 + c * 4];
                const float* r1 = &cur[(2 * m + 1) * 64 + c * 4];
                float a[8] = {r0[0], r0[1], r0[2], r0[3], r1[0], r1[1], r1[2], r1[3]};
                float s4[4] = {0, 0, 0, 0}, d4[4] = {0, 0, 0, 0};
#pragma unroll
                for (int r = 0; r < 8; ++r)
#pragma unroll
                    for (int kk = 0; kk < 4; ++kk) {
                        s4[kk] += a[r] * g_ecs[r][kk];
                        d4[kk] += a[r] * g_ecd[r][kk];
                    }
                size_t wrow = ((size_t)b * STRIDE_R + off + m) * 64 + c * 4;
                *(float4*)&g_sbuf[wrow] = make_float4(s4[0], s4[1], s4[2], s4[3]);
                *(float4*)&g_dbuf[wrow] = make_float4(d4[0], d4[1], d4[2], d4[3]);
                sv[qi] = make_float4(s4[0], s4[1], s4[2], s4[3]);
                has[qi] = 1;
            }
        }
        __syncthreads();
#pragma unroll
        for (int qi = 0; qi < 4; ++qi) {
            int q = t + qi * 256;
            if (has[qi]) {
                int c = q & 15, m = q >> 4;
                *(float4*)&cur[m * 64 + c * 4] = sv[qi];
            }
        }
        __syncthreads();
    }
}

// ---------------- forward truncated DFT, uniform 256-row blocks ----------------
// cu map: [0,16) lev0 x16 chunks; [16,24) lev1 x8; [24,28) lev2 x4;
//         [28,30) lev3 x2; [30,39) lev 4..12 x1.
__global__ void k_fwd_all() {
    int cu = blockIdx.x;
    int b = blockIdx.y;
    int which = blockIdx.z;
    int lev, ch, nch;
    if (cu < 16)      { lev = 0; ch = cu;      nch = 16; }
    else if (cu < 24) { lev = 1; ch = cu - 16; nch = 8; }
    else if (cu < 28) { lev = 2; ch = cu - 24; nch = 4; }
    else if (cu < 30) { lev = 3; ch = cu - 28; nch = 2; }
    else              { lev = cu - 26; ch = 0; nch = 1; }
    int M = 4096 >> lev;
    int off = NFULL - (NFULL >> lev);
    int l = M / 2 + 1; if (l > 64) l = 64;
    int chunk = M / nch;
    const float* src = (which ? g_sbuf : g_dbuf) + ((size_t)b * STRIDE_R + off) * 64;
    float* dst;
    if (nch == 1) {
        dst = (which ? g_ShatL : g_DhatL) + (size_t)lev * SPEC;
    } else {
        int ub = (lev == 0) ? 0 : (lev == 1) ? 16 : (lev == 2) ? 24 : 28;
        dst = (which ? g_partS : g_partD) + (size_t)(ub + ch) * SPEC;
    }
    const float* twc = g_twc + (size_t)off * 64;
    const float* tws = g_tws + (size_t)off * 64;
    int n0 = ch * chunk;
    int n1 = n0 + chunk;
    int t = threadIdx.x;
    int fr = t >> 4;
    int jc = t & 15;

    __shared__ float xs[32][64];
    __shared__ ull tw[64][32];   // (c, -s)

    ull acc[4][4];
#pragma unroll
    for (int u = 0; u < 4; ++u)
#pragma unroll
        for (int v = 0; v < 4; ++v) acc[u][v] = 0ULL;

    for (int nb = n0; nb < n1; nb += 32) {
        int cnt = n1 - nb; if (cnt > 32) cnt = 32;
        for (int q = t; q < cnt * 16; q += 256) {
            int nn = q >> 4, jj = (q & 15) << 2;
            *(float4*)&xs[nn][jj] = *(const float4*)&src[(size_t)(nb + nn) * 64 + jj];
        }
        for (int q = t; q < 2048; q += 256) {
            int f = q >> 5, nn = q & 31;
            float c = 0.0f, s = 0.0f;
            if (nn < cnt) { c = twc[f * M + nb + nn]; s = tws[f * M + nb + nn]; }
            tw[f][nn] = pack2(c, -s);
        }
        __syncthreads();
        if (cnt == 32) {
#pragma unroll 2
            for (int nn = 0; nn < 32; ++nn) {
                float4 xv = *(const float4*)&xs[nn][jc << 2];
                ull xx0 = pack2(xv.x, xv.x);
                ull xx1 = pack2(xv.y, xv.y);
                ull xx2 = pack2(xv.z, xv.z);
                ull xx3 = pack2(xv.w, xv.w);
#pragma unroll
                for (int u = 0; u < 4; ++u) {
                    ull csp = tw[fr + 16 * u][nn];
                    ffma2(acc[u][0], csp, xx0);
                    ffma2(acc[u][1], csp, xx1);
                    ffma2(acc[u][2], csp, xx2);
                    ffma2(acc[u][3], csp, xx3);
                }
            }
        } else {
            for (int nn = 0; nn < cnt; ++nn) {
                float4 xv = *(const float4*)&xs[nn][jc << 2];
                ull xx0 = pack2(xv.x, xv.x);
                ull xx1 = pack2(xv.y, xv.y);
                ull xx2 = pack2(xv.z, xv.z);
                ull xx3 = pack2(xv.w, xv.w);
#pragma unroll
                for (int u = 0; u < 4; ++u) {
                    ull csp = tw[fr + 16 * u][nn];
                    ffma2(acc[u][0], csp, xx0);
                    ffma2(acc[u][1], csp, xx1);
                    ffma2(acc[u][2], csp, xx2);
                    ffma2(acc[u][3], csp, xx3);
                }
            }
        }
        __syncthreads();
    }
#pragma unroll
    for (int u = 0; u < 4; ++u) {
        int f = fr + 16 * u;
        if (f < l) {
            size_t base = ((((size_t)b * 64 + f) * 64) + (jc << 2)) * 2;
            ulonglong2 s0; s0.x = acc[u][0]; s0.y = acc[u][1];
            ulonglong2 s1; s1.x = acc[u][2]; s1.y = acc[u][3];
            *(ulonglong2*)&dst[base]     = s0;
            *(ulonglong2*)&dst[base + 4] = s1;
        }
    }
}

// ---------------- per-mode complex mixing, all levels ----------------
// Chunk-partial reduction for levels 0..3 fused into the staging loop.
__global__ void k_mix_all() {
    int lev = blockIdx.x >> 6;
    int f = blockIdx.x & 63;
    int M = 4096 >> lev;
    int l = M / 2 + 1; if (l > 64) l = 64;
    if (f >= l) return;
    int b0 = blockIdx.y * 8;
    int t = threadIdx.x;
    const float2* D2 = (const float2*)(g_DhatL + (size_t)lev * SPEC);
    const float2* S2 = (const float2*)(g_ShatL + (size_t)lev * SPEC);
    __shared__ ull Dp[8][64], Dn[8][64], Sp[8][64], Sn[8][64];
    __shared__ float wsm[6][16][64];
    for (int q = t; q < 8 * 64; q += 256) {
        int bb = q >> 6, i = q & 63;
        size_t base = ((size_t)(b0 + bb) * 64 + f) * 64 + i;
        float2 dv, sv;
        if (lev < 4) {
            int nch = (lev == 0) ? 16 : (lev == 1) ? 8 : (lev == 2) ? 4 : 2;
            int ub  = (lev == 0) ? 0 : (lev == 1) ? 16 : (lev == 2) ? 24 : 28;
            float dr = 0.0f, di = 0.0f, sr = 0.0f, si = 0.0f;
            for (int c = 0; c < nch; ++c) {
                const float2* Pd = (const float2*)(g_partD + (size_t)(ub + c) * SPEC);
                const float2* Ps = (const float2*)(g_partS + (size_t)(ub + c) * SPEC);
                float2 a = Pd[base];
                float2 e = Ps[base];
                dr += a.x; di += a.y;
                sr += e.x; si += e.y;
            }
            dv = make_float2(dr, di);
            sv = make_float2(sr, si);
        } else {
            dv = D2[base];
            sv = S2[base];
        }
        Dp[bb][i] = pack2(dv.x, dv.y);
        Dn[bb][i] = pack2(-dv.y, dv.x);
        Sp[bb][i] = pack2(sv.x, sv.y);
        Sn[bb][i] = pack2(-sv.y, sv.x);
    }
    int o = t & 63;
    int bs = t >> 6;
    ull ud[2] = {0ULL, 0ULL}, us[2] = {0ULL, 0ULL};
    for (int ib = 0; ib < 64; ib += 16) {
        __syncthreads();
        for (int q = t; q < 16 * 64; q += 256) {
            int ii = q >> 6, oo = q & 63;
            int gi = f * 4096 + (ib + ii) * 64 + oo;
#pragma unroll
            for (int w = 0; w < 6; ++w) wsm[w][ii][oo] = g_wT[w][gi];
        }
        __syncthreads();
#pragma unroll 4
        for (int ii = 0; ii < 16; ++ii) {
            int i = ib + ii;
            float war = wsm[0][ii][o], wai = wsm[1][ii][o];
            float wbr = wsm[2][ii][o], wbi = wsm[3][ii][o];
            float wcr = wsm[4][ii][o], wci = wsm[5][ii][o];
            ull arr = pack2(war, war), aii = pack2(wai, wai);
            ull brr = pack2(wbr, wbr), bii = pack2(wbi, wbi);
            ull crr = pack2(wcr, wcr), cii = pack2(wci, wci);
#pragma unroll
            for (int q = 0; q < 2; ++q) {
                int bb = bs + 4 * q;
                ull dp = Dp[bb][i], dn = Dn[bb][i];
                ull sp = Sp[bb][i], sn = Sn[bb][i];
                ffma2(ud[q], arr, dp);
                ffma2(ud[q], aii, dn);
                ffma2(ud[q], brr, sp);
                ffma2(ud[q], bii, sn);
                ffma2(us[q], crr, dp);
                ffma2(us[q], cii, dn);
            }
        }
    }
    float alpha = (f == 0 || 2 * f == M) ? 1.0f : 2.0f;
    float sc = alpha / (float)M;
    float2* U2 = (float2*)(g_UdhatL + (size_t)lev * SPEC);
    float2* V2 = (float2*)(g_UshatL + (size_t)lev * SPEC);
#pragma unroll
    for (int q = 0; q < 2; ++q) {
        int b = b0 + bs + 4 * q;
        size_t base = ((size_t)b * 64 + f) * 64 + o;
        float ur, uv, vr, vv;
        unpack2(ud[q], ur, uv);
        unpack2(us[q], vr, vv);
        U2[base] = make_float2(ur * sc, uv * sc);
        V2[base] = make_float2(vr * sc, vv * sc);
    }
}

// ---------------- inverse DFT for deep levels 6..12 only -----------------------
__global__ void k_inv_deep() {
    int lev = 6 + blockIdx.x;
    int b = blockIdx.y;
    int which = blockIdx.z;
    int M = 4096 >> lev;
    int off = NFULL - (NFULL >> lev);
    int l = M / 2 + 1; if (l > 64) l = 64;
    const float4* spec4 = (const float4*)((which ? g_UshatL : g_UdhatL) + (size_t)lev * SPEC);
    float* out = (which ? g_Us : g_Ud) + ((size_t)b * STRIDE_R + off) * 64;
    const float* twc = g_twc + (size_t)off * 64;
    const float* tws = g_tws + (size_t)off * 64;
    int t = threadIdx.x;
    int nr = t >> 4;
    int jc = t & 15;

    __shared__ float Sr[32][64], Si[32][64];
    __shared__ float2 tw[64][32];

    ull acc[4][2];
#pragma unroll
    for (int u = 0; u < 4; ++u) { acc[u][0] = 0ULL; acc[u][1] = 0ULL; }

    for (int fb = 0; fb < l; fb += 32) {
        int cnt = l - fb; if (cnt > 32) cnt = 32;
        for (int q = t; q < cnt * 32; q += 256) {
            int ff = q >> 5, jp = (q & 31) << 1;
            float4 sv = spec4[((size_t)b * 64 + fb + ff) * 32 + (q & 31)];
            Sr[ff][jp] = sv.x; Si[ff][jp] = sv.y;
            Sr[ff][jp + 1] = sv.z; Si[ff][jp + 1] = sv.w;
        }
        for (int q = t; q < 2048; q += 256) {
            int nn = q & 63, ff = q >> 6;
            float c = 0.0f, s = 0.0f;
            if (ff < cnt && nn < M) { c = twc[(fb + ff) * M + nn]; s = tws[(fb + ff) * M + nn]; }
            tw[nn][ff] = make_float2(c, -s);
        }
        __syncthreads();
        for (int ff = 0; ff < cnt; ++ff) {
            ulonglong2 srp = *(const ulonglong2*)&Sr[ff][jc << 2];
            ulonglong2 sip = *(const ulonglong2*)&Si[ff][jc << 2];
#pragma unroll
            for (int u = 0; u < 4; ++u) {
                float2 cs = tw[nr + 16 * u][ff];
                ull cc = pack2(cs.x, cs.x);
                ull sn = pack2(cs.y, cs.y);
                ffma2(acc[u][0], cc, srp.x);
                ffma2(acc[u][0], sn, sip.x);
                ffma2(acc[u][1], cc, srp.y);
                ffma2(acc[u][1], sn, sip.y);
            }
        }
        __syncthreads();
    }
#pragma unroll
    for (int u = 0; u < 4; ++u) {
        int n = nr + 16 * u;
        if (n < M) {
            ulonglong2 st; st.x = acc[u][0]; st.y = acc[u][1];
            *(ulonglong2*)&out[(size_t)n * 64 + (jc << 2)] = st;
        }
    }
}

// ---------------- fused t0 + reconstruction for levels 12..6 -------------------
__global__ void k_deeprec(const float* __restrict__ t0w, const float* __restrict__ t0b) {
    extern __shared__ float dsm[];
    int b = blockIdx.x;
    int t = threadIdx.x;
    float* bufs0 = dsm;
    float* bufs1 = dsm + 8192;
    if (t < 16) {
        const float* row = g_sbuf + ((size_t)b * STRIDE_R + 8190) * 64 + t * 4;
        float in[4] = {row[0], row[1], row[2], row[3]};
#pragma unroll
        for (int kk = 0; kk < 4; ++kk) {
            float o = t0b[kk];
#pragma unroll
            for (int j = 0; j < 4; ++j) o += in[j] * t0w[kk * 4 + j];
            bufs0[t * 4 + kk] = o;
        }
    }
    __syncthreads();
    int parity = 0;
    for (int lev = 12; lev >= 6; --lev) {
        float* cur = parity ? bufs1 : bufs0;
        float* nxt = parity ? bufs0 : bufs1;
        int M = 4096 >> lev;
        int off = NFULL - (NFULL >> lev);
        int nu = M * 16;
#pragma unroll 1
        for (int q = t; q < nu; q += 256) {
            int c = q & 15, m = q >> 4;
            size_t grow = ((size_t)b * STRIDE_R + off + m) * 64 + c * 4;
            const float* us = &g_Us[grow];
            const float* ud = &g_Ud[grow];
            const float* xr = &cur[m * 64 + c * 4];
            float a[8] = {xr[0] + us[0], xr[1] + us[1], xr[2] + us[2], xr[3] + us[3],
                          ud[0], ud[1], ud[2], ud[3]};
            float e4[4] = {0, 0, 0, 0}, o4[4] = {0, 0, 0, 0};
#pragma unroll
            for (int r = 0; r < 8; ++r)
#pragma unroll
                for (int kk = 0; kk < 4; ++kk) {
                    e4[kk] += a[r] * g_rce[r][kk];
                    o4[kk] += a[r] * g_rco[r][kk];
                }
            *(float4*)&nxt[(2 * m) * 64 + c * 4]     = make_float4(e4[0], e4[1], e4[2], e4[3]);
            *(float4*)&nxt[(2 * m + 1) * 64 + c * 4] = make_float4(o4[0], o4[1], o4[2], o4[3]);
        }
        __syncthreads();
        parity ^= 1;
    }
    float* fin = parity ? bufs1 : bufs0;
    float* dst = g_sbuf + ((size_t)b * STRIDE_R + 7936) * 64;
    for (int q = t; q < 128 * 16; q += 256) {
        int r = q >> 4, c4 = (q & 15) << 2;
        *(float4*)&dst[r * 64 + c4] = *(const float4*)&fin[r * 64 + c4];
    }
}

// ---------------- fused inverse-DFT + reconstruction (levels 5..0) -------------
__global__ void k_invrec(float* __restrict__ xout, int ooff, int ostride, int lev) {
    int M = NFULL >> (lev + 1);
    int off = NFULL - (NFULL >> lev);
    int tile = blockIdx.x;
    int b = blockIdx.y;
    const float4* ud4 = (const float4*)(g_UdhatL + (size_t)lev * SPEC);
    const float4* us4 = (const float4*)(g_UshatL + (size_t)lev * SPEC);
    const float* twc = g_twc + (size_t)off * 64;
    const float* tws = g_tws + (size_t)off * 64;
    int n0 = tile * 64;
    int t = threadIdx.x;
    int nr = t >> 4;
    int jc = t & 15;

    __shared__ float Ur[32][64], Ui[32][64], Vr[32][64], Vi[32][64];
    __shared__ float2 tw[64][32];

    ull accU[4][2], accV[4][2];
#pragma unroll
    for (int u = 0; u < 4; ++u) {
        accU[u][0] = accU[u][1] = 0ULL;
        accV[u][0] = accV[u][1] = 0ULL;
    }

    for (int fb = 0; fb < 64; fb += 32) {
        for (int q = t; q < 32 * 32; q += 256) {
            int ff = q >> 5, jp = (q & 31) << 1;
            size_t sidx = ((size_t)b * 64 + fb + ff) * 32 + (q & 31);
            float4 uv = ud4[sidx];
            float4 vv = us4[sidx];
            Ur[ff][jp] = uv.x; Ui[ff][jp] = uv.y;
            Ur[ff][jp + 1] = uv.z; Ui[ff][jp + 1] = uv.w;
            Vr[ff][jp] = vv.x; Vi[ff][jp] = vv.y;
            Vr[ff][jp + 1] = vv.z; Vi[ff][jp + 1] = vv.w;
        }
        for (int q = t; q < 2048; q += 256) {
            int nn = q & 63, ff = q >> 6;
            int n = n0 + nn;
            float c = twc[(fb + ff) * M + n];
            float s = tws[(fb + ff) * M + n];
            tw[nn][ff] = make_float2(c, -s);
        }
        __syncthreads();
        for (int ff = 0; ff < 32; ++ff) {
            ulonglong2 urp = *(const ulonglong2*)&Ur[ff][jc << 2];
            ulonglong2 uip = *(const ulonglong2*)&Ui[ff][jc << 2];
            ulonglong2 vrp = *(const ulonglong2*)&Vr[ff][jc << 2];
            ulonglong2 vip = *(const ulonglong2*)&Vi[ff][jc << 2];
#pragma unroll
            for (int u = 0; u < 4; ++u) {
                float2 cs = tw[nr + 16 * u][ff];
                ull cc = pack2(cs.x, cs.x);
                ull sn = pack2(cs.y, cs.y);
                ffma2(accU[u][0], cc, urp.x);
                ffma2(accU[u][0], sn, uip.x);
                ffma2(accU[u][1], cc, urp.y);
                ffma2(accU[u][1], sn, uip.y);
                ffma2(accV[u][0], cc, vrp.x);
                ffma2(accV[u][0], sn, vip.x);
                ffma2(accV[u][1], cc, vrp.y);
                ffma2(accV[u][1], sn, vip.y);
            }
        }
        __syncthreads();
    }
#pragma unroll
    for (int u = 0; u < 4; ++u) {
        int n = n0 + nr + 16 * u;
        float udv[4], usv[4];
        unpack2(accU[u][0], udv[0], udv[1]);
        unpack2(accU[u][1], udv[2], udv[3]);
        unpack2(accV[u][0], usv[0], usv[1]);
        unpack2(accV[u][1], usv[2], usv[3]);
        float4 xv = *(const float4*)&g_sbuf[((size_t)b * STRIDE_R + off + n) * 64 + (jc << 2)];
        float a[8] = {xv.x + usv[0], xv.y + usv[1], xv.z + usv[2], xv.w + usv[3],
                      udv[0], udv[1], udv[2], udv[3]};
        float e4[4] = {0, 0, 0, 0}, o4[4] = {0, 0, 0, 0};
#pragma unroll
        for (int r = 0; r < 8; ++r)
#pragma unroll
            for (int kk = 0; kk < 4; ++kk) {
                e4[kk] += a[r] * g_rce[r][kk];
                o4[kk] += a[r] * g_rco[r][kk];
            }
        size_t orow = ((size_t)b * ostride + ooff + 2 * n) * 64 + (jc << 2);
        *(float4*)&xout[orow]      = make_float4(e4[0], e4[1], e4[2], e4[3]);
        *(float4*)&xout[orow + 64] = make_float4(o4[0], o4[1], o4[2], o4[3]);
    }
}

// ---------------- host orchestration (single stream) ----------------
extern "C" void kernel_launch(void* const* d_in, const int* in_sizes, int n_in,
                              void* d_out, int out_size) {
    (void)in_sizes; (void)n_in; (void)out_size;
    const float* x_in = (const float*)d_in[0];
    const float* wAre = (const float*)d_in[1];
    const float* wAim = (const float*)d_in[2];
    const float* wBre = (const float*)d_in[3];
    const float* wBim = (const float*)d_in[4];
    const float* wCre = (const float*)d_in[5];
    const float* wCim = (const float*)d_in[6];
    const float* t0w  = (const float*)d_in[7];
    const float* t0b  = (const float*)d_in[8];
    float* out = (float*)d_out;

    float* sbuf;
    cudaGetSymbolAddress((void**)&sbuf, g_sbuf);

    init_filters<<<1, 1>>>();
    fill_tw<<<(TWTOT + 255) / 256, 256>>>();
    k_transpose_w<<<(CKD * CKD * 64 + 255) / 256, 256>>>(wAre, wAim, wBre, wBim, wCre, wCim);

    // decomposition: levels 0..5 sequential, 6..12 fused
    for (int lev = 0; lev <= 5; ++lev) {
        int M = 4096 >> lev;
        int off = NFULL - (NFULL >> lev);
        int tot = BB * M * CC;
        if (lev == 0)
            k_decompose<<<(tot + 255) / 256, 256>>>(x_in, 0, NFULL, 0, M);
        else
            k_decompose<<<(tot + 255) / 256, 256>>>(sbuf, NFULL - (NFULL >> (lev - 1)),
                                                    STRIDE_R, off, M);
    }
    k_deepdec<<<BB, 256>>>();

    // batched spectral pipeline (uniform 256-row fwd blocks; reduce fused in mix)
    k_fwd_all<<<dim3(39, BB, 2), 256>>>();
    k_mix_all<<<dim3(NLEV * 64, 4), 256>>>();
    k_inv_deep<<<dim3(7, BB, 2), 256>>>();

    // reconstruction: t0 + levels 12..6 fused, then fused inv+recon for 5..0
    cudaFuncSetAttribute(k_deeprec, cudaFuncAttributeMaxDynamicSharedMemorySize, 65536);
    k_deeprec<<<BB, 256, 65536>>>(t0w, t0b);
    for (int lev = 5; lev >= 1; --lev) {
        int M = NFULL >> (lev + 1);
        k_invrec<<<dim3(M / 64, BB), 256>>>(sbuf, NFULL - (NFULL >> (lev - 1)), STRIDE_R, lev);
    }
    k_invrec<<<dim3(64, BB), 256>>>(out, 0, NFULL, 0);
}